// round 12
// baseline (speedup 1.0000x reference)
#include <cuda_runtime.h>
#include <cuda_fp16.h>
#include <math.h>
#include <stdint.h>

#define NIMG 10
#define BB 2
#define LL 5
#define CC 64
#define HH 100
#define WW 352
#define HW 35200
#define KSEL 8800

// ---- scratch (static device globals; no allocation) ----
__device__ float g_conf[NIMG * HW];    // sigmoid(max psm) map (bit-exact vs XLA)
__device__ float g_confw[NIMG * HW];   // warped confidence (bit-exact vs XLA)
__device__ float g_thr[NIMG];          // per-sample K-th largest conf value
__device__ float g_avg[BB * CC * HW];  // (1/L) * sum_l sparse_l, per batch
// conv weights per tap, fp16: [t][co][ci], padded to 50 taps (tap 49 = 0)
__device__ unsigned short g_wt[50 * CC * CC];

// scale constants, computed in double then rounded to f32 (matches Python)
#define S01 ((float)(100.0 / 352.0))
#define S02 ((float)(2.0 / (2.0 * 0.4 * 352.0)))
#define S10 ((float)(352.0 / 100.0))
#define S12 ((float)(2.0 / (2.0 * 0.4 * 100.0)))
#define CXW ((float)(2.0 / 352.0))
#define CYH ((float)(2.0 / 100.0))

// ============================================================
// mma.sync / ldmatrix helpers (baseline PTX, sm_80+; OK on sm_103 plain)
// ============================================================
static __device__ __forceinline__ uint32_t smem_u32(const void* p) {
    uint32_t a;
    asm("{ .reg .u64 t; cvta.to.shared.u64 t, %1; cvt.u32.u64 %0, t; }" : "=r"(a) : "l"(p));
    return a;
}

#define LDMATRIX_X4(r, addr) \
    asm volatile("ldmatrix.sync.aligned.m8n8.x4.shared.b16 {%0,%1,%2,%3}, [%4];" \
        : "=r"((r)[0]), "=r"((r)[1]), "=r"((r)[2]), "=r"((r)[3]) : "r"(addr))

#define LDMATRIX_X2(r, addr) \
    asm volatile("ldmatrix.sync.aligned.m8n8.x2.shared.b16 {%0,%1}, [%2];" \
        : "=r"((r)[0]), "=r"((r)[1]) : "r"(addr))

#define MMA_F16(d, a, bfr) \
    asm volatile("mma.sync.aligned.m16n8k16.row.col.f32.f16.f16.f32 " \
        "{%0,%1,%2,%3}, {%4,%5,%6,%7}, {%8,%9}, {%0,%1,%2,%3};" \
        : "+f"((d)[0]), "+f"((d)[1]), "+f"((d)[2]), "+f"((d)[3]) \
        : "r"((a)[0]), "r"((a)[1]), "r"((a)[2]), "r"((a)[3]), "r"((bfr)[0]), "r"((bfr)[1]))

// ---- XLA f32 tanh (Eigen-style rational approx, uncontracted mul/add) ----
__device__ __forceinline__ float xla_tanh(float x) {
    float cx = fminf(fmaxf(x, -7.90531110763549805f), 7.90531110763549805f);
    float x2 = __fmul_rn(cx, cx);
    float p = -2.76076847742355e-16f;
    p = __fadd_rn(__fmul_rn(p, x2), 2.00018790482477e-13f);
    p = __fadd_rn(__fmul_rn(p, x2), -8.60467152213735e-11f);
    p = __fadd_rn(__fmul_rn(p, x2), 5.12229709037114e-08f);
    p = __fadd_rn(__fmul_rn(p, x2), 1.48572235717979e-05f);
    p = __fadd_rn(__fmul_rn(p, x2), 6.37261928875436e-04f);
    p = __fadd_rn(__fmul_rn(p, x2), 4.89352455891786e-03f);
    float num = __fmul_rn(cx, p);
    float q = 1.19825839466702e-06f;
    q = __fadd_rn(__fmul_rn(q, x2), 1.18534705686654e-04f);
    q = __fadd_rn(__fmul_rn(q, x2), 2.26843463243900e-03f);
    q = __fadd_rn(__fmul_rn(q, x2), 4.89352518554385e-03f);
    float r = __fdiv_rn(num, q);
    return (fabsf(x) < 0.0004f) ? x : r;
}
__device__ __forceinline__ float xla_sigmoid(float x) {
    return __fadd_rn(0.5f, __fmul_rn(0.5f, xla_tanh(__fmul_rn(0.5f, x))));
}

__device__ __forceinline__ void get_theta(const float* __restrict__ pt, int b, int l, float th[6]) {
    const float* p = pt + b * (LL * LL * 16) + l * 16;
    th[0] = p[0];
    th[1] = p[1] * S01;
    th[2] = p[3] * S02;
    th[3] = p[4] * S10;
    th[4] = p[5];
    th[5] = p[7] * S12;
}

// ============================================================
// Kernel 0: conf map = sigmoid(max(psm over 2 ch)), elementwise, strict XLA.
// ============================================================
__global__ __launch_bounds__(256) void k_conf(const float* __restrict__ psm) {
    int i = blockIdx.x * 256 + threadIdx.x;
    if (i < NIMG * HW) {
        int n = i / HW, hw = i - n * HW;
        const float* base = psm + (size_t)n * 2 * HW;
        float m = fmaxf(base[hw], base[HW + hw]);
        g_conf[i] = xla_sigmoid(m);
    }
}

// ============================================================
// Kernel 1: warp conf map (gather-only; strict fp32 sequence).
// grid (H, N), block W
// ============================================================
__global__ __launch_bounds__(WW) void k_confwarp(const float* __restrict__ pt) {
    int h = blockIdx.x, n = blockIdx.y, w = threadIdx.x;
    int b = n / LL, l = n % LL;
    const float* p = pt + b * (LL * LL * 16) + l * 16;
    float th0 = p[0];
    float th1 = __fmul_rn(p[1], S01);
    float th2 = __fmul_rn(p[3], S02);
    float th3 = __fmul_rn(p[4], S10);
    float th4 = p[5];
    float th5 = __fmul_rn(p[7], S12);

    float gx = __fsub_rn(__fmul_rn(__fadd_rn((float)w, 0.5f), CXW), 1.0f);
    float gy = __fsub_rn(__fmul_rn(__fadd_rn((float)h, 0.5f), CYH), 1.0f);
    float src_x = __fadd_rn(__fadd_rn(__fmul_rn(th0, gx), __fmul_rn(th1, gy)), th2);
    float src_y = __fadd_rn(__fadd_rn(__fmul_rn(th3, gx), __fmul_rn(th4, gy)), th5);
    float px = __fsub_rn(__fmul_rn(__fadd_rn(src_x, 1.0f), 176.0f), 0.5f);
    float py = __fsub_rn(__fmul_rn(__fadd_rn(src_y, 1.0f), 50.0f), 0.5f);
    float x0 = floorf(px), y0 = floorf(py);
    float wx1 = __fsub_rn(px, x0), wx0 = __fsub_rn(1.0f, wx1);
    float wy1 = __fsub_rn(py, y0), wy0 = __fsub_rn(1.0f, wy1);

    const float* cmap = g_conf + (size_t)n * HW;
    float acc = 0.0f;
#pragma unroll
    for (int dy = 0; dy < 2; ++dy) {
#pragma unroll
        for (int dx = 0; dx < 2; ++dx) {
            float yy = dy ? __fadd_rn(y0, 1.0f) : y0;
            float xx = dx ? __fadd_rn(x0, 1.0f) : x0;
            if (yy >= 0.0f && yy <= (float)(HH - 1) && xx >= 0.0f && xx <= (float)(WW - 1)) {
                int yi = (int)yy, xi = (int)xx;
                float s = cmap[yi * WW + xi];
                float wgt = __fmul_rn(dy ? wy1 : wy0, dx ? wx1 : wx0);
                acc = __fadd_rn(acc, __fmul_rn(s, wgt));
            }
        }
    }
    g_confw[n * HW + h * WW + w] = acc;
}

// ============================================================
// Kernel 2: exact K-th largest via 8/12/11-bit radix select.
// Pass 1 (clustered exponent digit) uses PER-WARP PRIVATE histograms --
// cross-warp same-address ATOMS serialization (32cyc/warp) was the 38us.
// Keys staged to shared once. Values >= 0 so uint order == float order.
// ============================================================
#define SEL_SMEM ((HW + 32 * 256 + 256) * 4)

__device__ __forceinline__ void agg_inc(unsigned int* hist, unsigned int bin, unsigned int mask) {
    unsigned int peers = __match_any_sync(mask, bin);
    unsigned int lane = threadIdx.x & 31;
    unsigned int leader = __ffs(peers) - 1;
    if (lane == leader) atomicAdd(&hist[bin], __popc(peers));
}

__global__ __launch_bounds__(1024) void k_select() {
    extern __shared__ unsigned int sbuf[];
    unsigned int* keys  = sbuf;                 // HW keys
    unsigned int* whist = sbuf + HW;            // 32 warps x 256 bins (pass1); reused 4096/2048
    unsigned int* tot   = sbuf + HW + 8192;     // 256 reduced bins
    __shared__ unsigned int ssum[64];
    __shared__ unsigned int s_sel, s_krem;
    int n = blockIdx.x;
    const unsigned int* v = (const unsigned int*)(g_confw + (size_t)n * HW);
    int tid = threadIdx.x;
    int wid = tid >> 5;

    for (int i = tid; i < 8192; i += 1024) whist[i] = 0u;
    __syncthreads();

    // ---- pass 1: stage keys + 8-bit digit (bits 23..30) into PRIVATE warp hist ----
    unsigned int* myh = whist + wid * 256;
    for (int base = 0; base < 34 * 1024; base += 1024) {
        unsigned int key = v[base + tid];
        keys[base + tid] = key;
        agg_inc(myh, key >> 23, 0xFFFFFFFFu);
    }
    if (tid < 384) {   // warps 0..11 fully active
        unsigned int key = v[34 * 1024 + tid];
        keys[34 * 1024 + tid] = key;
        agg_inc(myh, key >> 23, 0xFFFFFFFFu);
    }
    __syncthreads();
    // reduce 32 private hists
    if (tid < 256) {
        unsigned int s = 0;
#pragma unroll
        for (int w = 0; w < 32; ++w) s += whist[w * 256 + tid];
        tot[tid] = s;
    }
    __syncthreads();
    // pick among 256 (two-level 16x16)
    if (tid < 16) {
        unsigned int s = 0;
        for (int j = 0; j < 16; ++j) s += tot[tid * 16 + j];
        ssum[tid] = s;
    }
    __syncthreads();
    if (tid == 0) {
        unsigned int krem = KSEL;
        int sb = 15;
        for (;; --sb) { if (ssum[sb] >= krem) break; krem -= ssum[sb]; }
        int bin = sb * 16 + 15;
        for (;; --bin) { unsigned int c = tot[bin]; if (c >= krem) break; krem -= c; }
        s_sel = (unsigned int)bin; s_krem = krem;
    }
    __syncthreads();
    unsigned int sel8 = s_sel, krem1 = s_krem;

    // ---- pass 2: 12-bit digit (bits 11..22) among prefix matches (mantissa: spread) ----
    for (int i = tid; i < 4096; i += 1024) whist[i] = 0u;
    __syncthreads();
    for (int base = 0; base < 34 * 1024; base += 1024) {
        unsigned int key = keys[base + tid];
        bool pr = ((key >> 23) == sel8);
        unsigned int mask = __ballot_sync(0xFFFFFFFFu, pr);
        if (pr) agg_inc(whist, (key >> 11) & 0xFFFu, mask);
    }
    {
        bool act = tid < 384;
        unsigned int key = act ? keys[34 * 1024 + tid] : 0u;
        bool pr = act && ((key >> 23) == sel8);
        unsigned int mask = __ballot_sync(0xFFFFFFFFu, pr);
        if (pr) agg_inc(whist, (key >> 11) & 0xFFFu, mask);
    }
    __syncthreads();
    if (tid < 64) {
        unsigned int s = 0;
        for (int j = 0; j < 64; ++j) s += whist[tid * 64 + j];
        ssum[tid] = s;
    }
    __syncthreads();
    if (tid == 0) {
        unsigned int krem = krem1;
        int sb = 63;
        for (;; --sb) { if (ssum[sb] >= krem) break; krem -= ssum[sb]; }
        int bin = sb * 64 + 63;
        for (;; --bin) { unsigned int c = whist[bin]; if (c >= krem) break; krem -= c; }
        s_sel = (unsigned int)bin; s_krem = krem;
    }
    __syncthreads();
    unsigned int pfx20 = (sel8 << 12) | s_sel;   // = key >> 11
    unsigned int krem2 = s_krem;

    // ---- pass 3: 11-bit digit (bits 0..10) among prefix matches ----
    for (int i = tid; i < 2048; i += 1024) whist[i] = 0u;
    __syncthreads();
    for (int base = 0; base < 34 * 1024; base += 1024) {
        unsigned int key = keys[base + tid];
        bool pr = ((key >> 11) == pfx20);
        unsigned int mask = __ballot_sync(0xFFFFFFFFu, pr);
        if (pr) agg_inc(whist, key & 0x7FFu, mask);
    }
    {
        bool act = tid < 384;
        unsigned int key = act ? keys[34 * 1024 + tid] : 0u;
        bool pr = act && ((key >> 11) == pfx20);
        unsigned int mask = __ballot_sync(0xFFFFFFFFu, pr);
        if (pr) agg_inc(whist, key & 0x7FFu, mask);
    }
    __syncthreads();
    if (tid < 64) {
        unsigned int s = 0;
        for (int j = 0; j < 32; ++j) s += whist[tid * 32 + j];
        ssum[tid] = s;
    }
    __syncthreads();
    if (tid == 0) {
        unsigned int krem = krem2;
        int sb = 63;
        for (;; --sb) { if (ssum[sb] >= krem) break; krem -= ssum[sb]; }
        int bin = sb * 32 + 31;
        for (;; --bin) { unsigned int c = whist[bin]; if (c >= krem) break; krem -= c; }
        g_thr[n] = __uint_as_float((pfx20 << 11) | (unsigned int)bin);
    }
}

// ============================================================
// Kernel 3: warp x + mask + (1/L)-accumulate over l. grid (H, 4, B), block W
// (R8 known-good config: 16 channels/thread)
// ============================================================
__global__ __launch_bounds__(WW) void k_warpacc(const float* __restrict__ x,
                                                const float* __restrict__ pt) {
    int h = blockIdx.x, cg = blockIdx.y, b = blockIdx.z, w = threadIdx.x;
    float acc[16];
#pragma unroll
    for (int i = 0; i < 16; ++i) acc[i] = 0.0f;
    float gx = (w + 0.5f) * (2.0f / WW) - 1.0f;
    float gy = (h + 0.5f) * (2.0f / HH) - 1.0f;
    for (int l = 0; l < LL; ++l) {
        int n = b * LL + l;
        if (l != 0 && g_confw[n * HW + h * WW + w] < g_thr[n]) continue;
        float th[6];
        get_theta(pt, b, l, th);
        float px = (th[0] * gx + th[1] * gy + th[2] + 1.0f) * (WW * 0.5f) - 0.5f;
        float py = (th[3] * gx + th[4] * gy + th[5] + 1.0f) * (HH * 0.5f) - 0.5f;
        float x0 = floorf(px), y0 = floorf(py);
        float wx1 = px - x0, wx0 = 1.0f - wx1;
        float wy1 = py - y0, wy0 = 1.0f - wy1;
        bool vx0 = (x0 >= 0.0f) && (x0 <= (float)(WW - 1));
        bool vx1 = (x0 + 1.0f >= 0.0f) && (x0 + 1.0f <= (float)(WW - 1));
        bool vy0 = (y0 >= 0.0f) && (y0 <= (float)(HH - 1));
        bool vy1 = (y0 + 1.0f >= 0.0f) && (y0 + 1.0f <= (float)(HH - 1));
        int x0i = (int)fminf(fmaxf(x0, 0.0f), (float)(WW - 1));
        int x1i = (int)fminf(fmaxf(x0 + 1.0f, 0.0f), (float)(WW - 1));
        int y0i = (int)fminf(fmaxf(y0, 0.0f), (float)(HH - 1));
        int y1i = (int)fminf(fmaxf(y0 + 1.0f, 0.0f), (float)(HH - 1));
        float m00 = (vy0 && vx0) ? wy0 * wx0 * 0.2f : 0.0f;
        float m01 = (vy0 && vx1) ? wy0 * wx1 * 0.2f : 0.0f;
        float m10 = (vy1 && vx0) ? wy1 * wx0 * 0.2f : 0.0f;
        float m11 = (vy1 && vx1) ? wy1 * wx1 * 0.2f : 0.0f;
        int i00 = y0i * WW + x0i, i01 = y0i * WW + x1i;
        int i10 = y1i * WW + x0i, i11 = y1i * WW + x1i;
        const float* xb = x + (size_t)(n * CC + cg * 16) * HW;
#pragma unroll
        for (int c = 0; c < 16; ++c) {
            const float* xc = xb + c * HW;
            acc[c] += xc[i00] * m00 + xc[i01] * m01 + xc[i10] * m10 + xc[i11] * m11;
        }
    }
    int outbase = ((b * CC + cg * 16) * HH + h) * WW + w;
#pragma unroll
    for (int c = 0; c < 16; ++c) g_avg[outbase + c * HW] = acc[c];
}

// ============================================================
// Kernel 3b: weights -> fp16 per tap: g_wt[t][co][ci]. grid 50 (tap 49 = 0).
// ============================================================
__global__ __launch_bounds__(256) void k_prepw(const float* __restrict__ fw) {
    int t = blockIdx.x;
    for (int e = threadIdx.x; e < CC * CC; e += 256) {
        int co = e >> 6, ci = e & 63;
        float v = (t < 49) ? fw[(size_t)(co * CC + ci) * 49 + t] : 0.0f;
        g_wt[(size_t)t * (CC * CC) + e] = __half_as_ushort(__float2half_rn(v));
    }
}

// ============================================================
// Kernel 4: 7x7 conv via mma.sync implicit GEMM, taps-outer / K=ci.
// R8 known-good config: single-pass fp16, 25 two-tap stages, 2 blocks/SM.
// ============================================================
#define ASTRIDE 144
#define AS_SZ 54720                       // 380 * 144
#define BS_OFF(buf) (AS_SZ + (buf) * 18432)
#define SMEM_TC 91584

__global__ void __launch_bounds__(256, 2) k_conv_mma(float* __restrict__ out,
                                                     const float* __restrict__ bias) {
    extern __shared__ unsigned char smem[];
    uint32_t sb = smem_u32(smem);
    int tid = threadIdx.x;
    int lane = tid & 31, wrp = tid >> 5;
    int mw = wrp & 3, nw = wrp >> 2;
    int b = blockIdx.z;
    int h0 = blockIdx.y * 4, w0 = blockIdx.x * 32;

    float acc[2][4][4];
#pragma unroll
    for (int mt = 0; mt < 2; ++mt)
#pragma unroll
        for (int nt = 0; nt < 4; ++nt)
#pragma unroll
            for (int r = 0; r < 4; ++r) acc[mt][nt][r] = 0.0f;

    int tl = lane >> 3;
    int a_roff = (lane & 7) + (tl & 1) * 8;
    int a_coff = (tl >> 1) * 8;
    int b_roff = lane & 7;
    int b_coff = ((lane >> 3) & 1) * 8;

    uint32_t aBase[2];
#pragma unroll
    for (int mt = 0; mt < 2; ++mt) {
        int px = mw * 32 + mt * 16 + a_roff;
        int pr = px >> 5, pc = px & 31;
        aBase[mt] = sb + (uint32_t)(pr * 38 + pc) * ASTRIDE + (uint32_t)a_coff * 2;
    }
    uint32_t bBase = (uint32_t)(nw * 32 + b_roff) * ASTRIDE + (uint32_t)b_coff * 2;

    int b_co0 = tid >> 3, b_f4 = tid & 7;

    const float* inb = g_avg + (size_t)b * CC * HW;

    // ---- build A_ext once: 380 ext px x 64 ci, fp16 ----
#pragma unroll 4
    for (int it = 0; it < 96; ++it) {
        int idx = tid + it * 256;                 // 0..24575 = 64 ci * 384 slots
        int ci = idx / 384, p = idx - ci * 384;
        if (p < 380) {
            int er = p / 38, ec = p - er * 38;
            int gh = h0 - 3 + er, gw = w0 - 3 + ec;
            float v = 0.0f;
            if (gh >= 0 && gh < HH && gw >= 0 && gw < WW) v = inb[(size_t)ci * HW + gh * WW + gw];
            *(unsigned short*)(smem + p * ASTRIDE + ci * 2) =
                __half_as_ushort(__float2half_rn(v));
        }
    }
    // ---- stage B taps 0,1 into buffer 0 ----
    {
        const float4* s0 = (const float4*)(g_wt);
        const float4* s1 = (const float4*)(g_wt + (size_t)1 * (CC * CC));
        float4* d0 = (float4*)(smem + BS_OFF(0));
        float4* d1 = (float4*)(smem + BS_OFF(0) + 9216);
        d0[b_co0 * 9 + b_f4] = s0[tid];
        d0[(b_co0 + 32) * 9 + b_f4] = s0[tid + 256];
        d1[b_co0 * 9 + b_f4] = s1[tid];
        d1[(b_co0 + 32) * 9 + b_f4] = s1[tid + 256];
    }
    __syncthreads();

    for (int s = 0; s < 25; ++s) {
        int buf = s & 1;
        bool have_next = (s + 1 < 25);
        float4 v00, v01, v10, v11;
        if (have_next) {
            const float4* s0 = (const float4*)(g_wt + (size_t)(2 * s + 2) * (CC * CC));
            const float4* s1 = (const float4*)(g_wt + (size_t)(2 * s + 3) * (CC * CC));
            v00 = s0[tid]; v01 = s0[tid + 256];
            v10 = s1[tid]; v11 = s1[tid + 256];
        }

#pragma unroll
        for (int ti = 0; ti < 2; ++ti) {
            int t = 2 * s + ti;
            int toff = (t < 49) ? ((t / 7) * 38 + (t % 7)) * ASTRIDE : 0;  // pad tap: w=0
            uint32_t bptr = sb + BS_OFF(buf) + (uint32_t)ti * 9216 + bBase;
#pragma unroll
            for (int j = 0; j < 4; ++j) {
                uint32_t Ah[2][4];
#pragma unroll
                for (int mt = 0; mt < 2; ++mt)
                    LDMATRIX_X4(Ah[mt], aBase[mt] + (uint32_t)toff + (uint32_t)j * 32);
#pragma unroll
                for (int nt = 0; nt < 4; ++nt) {
                    uint32_t Bf[2];
                    LDMATRIX_X2(Bf, bptr + (uint32_t)(nt * 8) * ASTRIDE + (uint32_t)j * 32);
#pragma unroll
                    for (int mt = 0; mt < 2; ++mt)
                        MMA_F16(acc[mt][nt], Ah[mt], Bf);
                }
            }
        }

        if (have_next) {
            int nb = buf ^ 1;
            float4* d0 = (float4*)(smem + BS_OFF(nb));
            float4* d1 = (float4*)(smem + BS_OFF(nb) + 9216);
            d0[b_co0 * 9 + b_f4] = v00;
            d0[(b_co0 + 32) * 9 + b_f4] = v01;
            d1[b_co0 * 9 + b_f4] = v10;
            d1[(b_co0 + 32) * 9 + b_f4] = v11;
        }
        __syncthreads();
    }

    // ---- epilogue ----
    int g = lane >> 2, tig = lane & 3;
    float* o = out + (size_t)b * CC * HW;
#pragma unroll
    for (int mt = 0; mt < 2; ++mt) {
        int r0 = mw * 32 + mt * 16 + g;
        int oh0 = h0 + (r0 >> 5), ow0 = w0 + (r0 & 31);
        int r1 = r0 + 8;
        int oh1 = h0 + (r1 >> 5), ow1 = w0 + (r1 & 31);
#pragma unroll
        for (int nt = 0; nt < 4; ++nt) {
            int co = nw * 32 + nt * 8 + tig * 2;
            float bv0 = __ldg(&bias[co]), bv1 = __ldg(&bias[co + 1]);
            o[(size_t)co * HW + oh0 * WW + ow0] = acc[mt][nt][0] + bv0;
            o[(size_t)(co + 1) * HW + oh0 * WW + ow0] = acc[mt][nt][1] + bv1;
            o[(size_t)co * HW + oh1 * WW + ow1] = acc[mt][nt][2] + bv0;
            o[(size_t)(co + 1) * HW + oh1 * WW + ow1] = acc[mt][nt][3] + bv1;
        }
    }
}

// ============================================================
extern "C" void kernel_launch(void* const* d_in, const int* in_sizes, int n_in,
                              void* d_out, int out_size) {
    const float* x   = (const float*)d_in[0];  // (10,64,100,352)
    const float* psm = (const float*)d_in[1];  // (10,2,100,352)
    // d_in[2] record_len: unused
    const float* pt  = (const float*)d_in[3];  // (2,5,5,4,4)
    const float* fw  = (const float*)d_in[4];  // (64,64,7,7)
    const float* fb  = (const float*)d_in[5];  // (64,)
    float* out = (float*)d_out;                // (2,64,100,352)

    cudaFuncSetAttribute(k_conv_mma, cudaFuncAttributeMaxDynamicSharedMemorySize, SMEM_TC);
    cudaFuncSetAttribute(k_select, cudaFuncAttributeMaxDynamicSharedMemorySize, SEL_SMEM);

    k_prepw<<<50, 256>>>(fw);
    k_conf<<<(NIMG * HW + 255) / 256, 256>>>(psm);
    k_confwarp<<<dim3(HH, NIMG), WW>>>(pt);
    k_select<<<NIMG, 1024, SEL_SMEM>>>();
    k_warpacc<<<dim3(HH, 4, BB), WW>>>(x, pt);
    k_conv_mma<<<dim3(WW / 32, HH / 4, BB), 256, SMEM_TC>>>(out, fb);
}

// round 13
// speedup vs baseline: 1.1046x; 1.1046x over previous
#include <cuda_runtime.h>
#include <cuda_fp16.h>
#include <math.h>
#include <stdint.h>

#define NIMG 10
#define BB 2
#define LL 5
#define CC 64
#define HH 100
#define WW 352
#define HW 35200
#define KSEL 8800

// ---- scratch (static device globals; no allocation) ----
__device__ float g_confw[NIMG * HW];   // warped confidence (bit-exact vs XLA)
__device__ float g_thr[NIMG];          // per-sample K-th largest conf value
__device__ float g_avg[BB * CC * HW];  // (1/L) * sum_l sparse_l, per batch
// conv weights per tap, fp16: [t][co][ci], padded to 50 taps (tap 49 = 0)
__device__ unsigned short g_wt[50 * CC * CC];

// scale constants, computed in double then rounded to f32 (matches Python)
#define S01 ((float)(100.0 / 352.0))
#define S02 ((float)(2.0 / (2.0 * 0.4 * 352.0)))
#define S10 ((float)(352.0 / 100.0))
#define S12 ((float)(2.0 / (2.0 * 0.4 * 100.0)))
#define CXW ((float)(2.0 / 352.0))
#define CYH ((float)(2.0 / 100.0))

// ============================================================
// mma.sync / ldmatrix helpers (baseline PTX, sm_80+; OK on sm_103 plain)
// ============================================================
static __device__ __forceinline__ uint32_t smem_u32(const void* p) {
    uint32_t a;
    asm("{ .reg .u64 t; cvta.to.shared.u64 t, %1; cvt.u32.u64 %0, t; }" : "=r"(a) : "l"(p));
    return a;
}

#define LDMATRIX_X4(r, addr) \
    asm volatile("ldmatrix.sync.aligned.m8n8.x4.shared.b16 {%0,%1,%2,%3}, [%4];" \
        : "=r"((r)[0]), "=r"((r)[1]), "=r"((r)[2]), "=r"((r)[3]) : "r"(addr))

#define LDMATRIX_X2(r, addr) \
    asm volatile("ldmatrix.sync.aligned.m8n8.x2.shared.b16 {%0,%1}, [%2];" \
        : "=r"((r)[0]), "=r"((r)[1]) : "r"(addr))

#define MMA_F16(d, a, bfr) \
    asm volatile("mma.sync.aligned.m16n8k16.row.col.f32.f16.f16.f32 " \
        "{%0,%1,%2,%3}, {%4,%5,%6,%7}, {%8,%9}, {%0,%1,%2,%3};" \
        : "+f"((d)[0]), "+f"((d)[1]), "+f"((d)[2]), "+f"((d)[3]) \
        : "r"((a)[0]), "r"((a)[1]), "r"((a)[2]), "r"((a)[3]), "r"((bfr)[0]), "r"((bfr)[1]))

// ---- XLA f32 tanh (Eigen-style rational approx, uncontracted mul/add) ----
__device__ __forceinline__ float xla_tanh(float x) {
    float cx = fminf(fmaxf(x, -7.90531110763549805f), 7.90531110763549805f);
    float x2 = __fmul_rn(cx, cx);
    float p = -2.76076847742355e-16f;
    p = __fadd_rn(__fmul_rn(p, x2), 2.00018790482477e-13f);
    p = __fadd_rn(__fmul_rn(p, x2), -8.60467152213735e-11f);
    p = __fadd_rn(__fmul_rn(p, x2), 5.12229709037114e-08f);
    p = __fadd_rn(__fmul_rn(p, x2), 1.48572235717979e-05f);
    p = __fadd_rn(__fmul_rn(p, x2), 6.37261928875436e-04f);
    p = __fadd_rn(__fmul_rn(p, x2), 4.89352455891786e-03f);
    float num = __fmul_rn(cx, p);
    float q = 1.19825839466702e-06f;
    q = __fadd_rn(__fmul_rn(q, x2), 1.18534705686654e-04f);
    q = __fadd_rn(__fmul_rn(q, x2), 2.26843463243900e-03f);
    q = __fadd_rn(__fmul_rn(q, x2), 4.89352518554385e-03f);
    float r = __fdiv_rn(num, q);
    return (fabsf(x) < 0.0004f) ? x : r;
}
__device__ __forceinline__ float xla_sigmoid(float x) {
    return __fadd_rn(0.5f, __fmul_rn(0.5f, xla_tanh(__fmul_rn(0.5f, x))));
}

__device__ __forceinline__ void get_theta(const float* __restrict__ pt, int b, int l, float th[6]) {
    const float* p = pt + b * (LL * LL * 16) + l * 16;
    th[0] = p[0];
    th[1] = p[1] * S01;
    th[2] = p[3] * S02;
    th[3] = p[4] * S10;
    th[4] = p[5];
    th[5] = p[7] * S12;
}

// ============================================================
// Kernel 1 (R8 exact): warp conf = sigmoid(max psm), strict XLA fp32.
// grid (H, LL) per batch; base = first sample of this batch.
// ============================================================
__global__ __launch_bounds__(WW) void k_confwarp(const float* __restrict__ psm,
                                                 const float* __restrict__ pt, int base) {
    int h = blockIdx.x, n = base + blockIdx.y, w = threadIdx.x;
    int b = n / LL, l = n % LL;
    const float* p = pt + b * (LL * LL * 16) + l * 16;
    float th0 = p[0];
    float th1 = __fmul_rn(p[1], S01);
    float th2 = __fmul_rn(p[3], S02);
    float th3 = __fmul_rn(p[4], S10);
    float th4 = p[5];
    float th5 = __fmul_rn(p[7], S12);

    float gx = __fsub_rn(__fmul_rn(__fadd_rn((float)w, 0.5f), CXW), 1.0f);
    float gy = __fsub_rn(__fmul_rn(__fadd_rn((float)h, 0.5f), CYH), 1.0f);
    float src_x = __fadd_rn(__fadd_rn(__fmul_rn(th0, gx), __fmul_rn(th1, gy)), th2);
    float src_y = __fadd_rn(__fadd_rn(__fmul_rn(th3, gx), __fmul_rn(th4, gy)), th5);
    float px = __fsub_rn(__fmul_rn(__fadd_rn(src_x, 1.0f), 176.0f), 0.5f);
    float py = __fsub_rn(__fmul_rn(__fadd_rn(src_y, 1.0f), 50.0f), 0.5f);
    float x0 = floorf(px), y0 = floorf(py);
    float wx1 = __fsub_rn(px, x0), wx0 = __fsub_rn(1.0f, wx1);
    float wy1 = __fsub_rn(py, y0), wy0 = __fsub_rn(1.0f, wy1);

    const float* basep = psm + (size_t)n * 2 * HW;
    float acc = 0.0f;
#pragma unroll
    for (int dy = 0; dy < 2; ++dy) {
#pragma unroll
        for (int dx = 0; dx < 2; ++dx) {
            float yy = dy ? __fadd_rn(y0, 1.0f) : y0;
            float xx = dx ? __fadd_rn(x0, 1.0f) : x0;
            if (yy >= 0.0f && yy <= (float)(HH - 1) && xx >= 0.0f && xx <= (float)(WW - 1)) {
                int yi = (int)yy, xi = (int)xx;
                float m = fmaxf(basep[yi * WW + xi], basep[HW + yi * WW + xi]);
                float s = xla_sigmoid(m);
                float wgt = __fmul_rn(dy ? wy1 : wy0, dx ? wx1 : wx0);
                acc = __fadd_rn(acc, __fmul_rn(s, wgt));
            }
        }
    }
    g_confw[n * HW + h * WW + w] = acc;
}

// ============================================================
// Kernel 2 (R8 exact): K-th largest via 4x8-bit MSB radix select.
// grid LL per batch.
// ============================================================
__global__ __launch_bounds__(1024) void k_select(int base) {
    int n = base + blockIdx.x;
    const float* v = g_confw + (size_t)n * HW;
    __shared__ unsigned int hist[256];
    __shared__ unsigned int s_prefix, s_krem;
    if (threadIdx.x == 0) { s_prefix = 0u; s_krem = KSEL; }
    __syncthreads();
    for (int pass = 0; pass < 4; ++pass) {
        int shift = 24 - pass * 8;
        unsigned int pmask = (pass == 0) ? 0u : (0xFFFFFFFFu << (shift + 8));
        for (int i = threadIdx.x; i < 256; i += blockDim.x) hist[i] = 0u;
        __syncthreads();
        unsigned int prefix = s_prefix;
        for (int i = threadIdx.x; i < HW; i += blockDim.x) {
            unsigned int key = __float_as_uint(v[i]);
            if ((key & pmask) == prefix) atomicAdd(&hist[(key >> shift) & 255u], 1u);
        }
        __syncthreads();
        if (threadIdx.x == 0) {
            unsigned int krem = s_krem, c = 0u; int sel = 0;
            for (int bin = 255; bin >= 0; --bin) {
                c += hist[bin];
                if (c >= krem) { sel = bin; krem -= (c - hist[bin]); break; }
            }
            s_prefix = prefix | ((unsigned int)sel << shift);
            s_krem = krem;
        }
        __syncthreads();
    }
    if (threadIdx.x == 0) g_thr[n] = __uint_as_float(s_prefix);
}

// ============================================================
// Kernel 3 (R8 exact): warp x + mask + (1/L)-accumulate over l.
// grid (H, 4, 1) per batch.
// ============================================================
__global__ __launch_bounds__(WW) void k_warpacc(const float* __restrict__ x,
                                                const float* __restrict__ pt, int b) {
    int h = blockIdx.x, cg = blockIdx.y, w = threadIdx.x;
    float acc[16];
#pragma unroll
    for (int i = 0; i < 16; ++i) acc[i] = 0.0f;
    float gx = (w + 0.5f) * (2.0f / WW) - 1.0f;
    float gy = (h + 0.5f) * (2.0f / HH) - 1.0f;
    for (int l = 0; l < LL; ++l) {
        int n = b * LL + l;
        if (l != 0 && g_confw[n * HW + h * WW + w] < g_thr[n]) continue;
        float th[6];
        get_theta(pt, b, l, th);
        float px = (th[0] * gx + th[1] * gy + th[2] + 1.0f) * (WW * 0.5f) - 0.5f;
        float py = (th[3] * gx + th[4] * gy + th[5] + 1.0f) * (HH * 0.5f) - 0.5f;
        float x0 = floorf(px), y0 = floorf(py);
        float wx1 = px - x0, wx0 = 1.0f - wx1;
        float wy1 = py - y0, wy0 = 1.0f - wy1;
        bool vx0 = (x0 >= 0.0f) && (x0 <= (float)(WW - 1));
        bool vx1 = (x0 + 1.0f >= 0.0f) && (x0 + 1.0f <= (float)(WW - 1));
        bool vy0 = (y0 >= 0.0f) && (y0 <= (float)(HH - 1));
        bool vy1 = (y0 + 1.0f >= 0.0f) && (y0 + 1.0f <= (float)(HH - 1));
        int x0i = (int)fminf(fmaxf(x0, 0.0f), (float)(WW - 1));
        int x1i = (int)fminf(fmaxf(x0 + 1.0f, 0.0f), (float)(WW - 1));
        int y0i = (int)fminf(fmaxf(y0, 0.0f), (float)(HH - 1));
        int y1i = (int)fminf(fmaxf(y0 + 1.0f, 0.0f), (float)(HH - 1));
        float m00 = (vy0 && vx0) ? wy0 * wx0 * 0.2f : 0.0f;
        float m01 = (vy0 && vx1) ? wy0 * wx1 * 0.2f : 0.0f;
        float m10 = (vy1 && vx0) ? wy1 * wx0 * 0.2f : 0.0f;
        float m11 = (vy1 && vx1) ? wy1 * wx1 * 0.2f : 0.0f;
        int i00 = y0i * WW + x0i, i01 = y0i * WW + x1i;
        int i10 = y1i * WW + x0i, i11 = y1i * WW + x1i;
        const float* xb = x + (size_t)(n * CC + cg * 16) * HW;
#pragma unroll
        for (int c = 0; c < 16; ++c) {
            const float* xc = xb + c * HW;
            acc[c] += xc[i00] * m00 + xc[i01] * m01 + xc[i10] * m10 + xc[i11] * m11;
        }
    }
    int outbase = ((b * CC + cg * 16) * HH + h) * WW + w;
#pragma unroll
    for (int c = 0; c < 16; ++c) g_avg[outbase + c * HW] = acc[c];
}

// ============================================================
// Kernel 3b (R8 exact): weights -> fp16 per tap. grid 50 (tap 49 = 0).
// ============================================================
__global__ __launch_bounds__(256) void k_prepw(const float* __restrict__ fw) {
    int t = blockIdx.x;
    for (int e = threadIdx.x; e < CC * CC; e += 256) {
        int co = e >> 6, ci = e & 63;
        float v = (t < 49) ? fw[(size_t)(co * CC + ci) * 49 + t] : 0.0f;
        g_wt[(size_t)t * (CC * CC) + e] = __half_as_ushort(__float2half_rn(v));
    }
}

// ============================================================
// Kernel 4 (R8 exact): 7x7 conv via mma.sync implicit GEMM, taps-outer.
// Single-pass fp16, 25 two-tap stages, 2 blocks/SM. grid (11, 25, 1)/batch.
// ============================================================
#define ASTRIDE 144
#define AS_SZ 54720                       // 380 * 144
#define BS_OFF(buf) (AS_SZ + (buf) * 18432)
#define SMEM_TC 91584

__global__ void __launch_bounds__(256, 2) k_conv_mma(float* __restrict__ out,
                                                     const float* __restrict__ bias, int b) {
    extern __shared__ unsigned char smem[];
    uint32_t sb = smem_u32(smem);
    int tid = threadIdx.x;
    int lane = tid & 31, wrp = tid >> 5;
    int mw = wrp & 3, nw = wrp >> 2;
    int h0 = blockIdx.y * 4, w0 = blockIdx.x * 32;

    float acc[2][4][4];
#pragma unroll
    for (int mt = 0; mt < 2; ++mt)
#pragma unroll
        for (int nt = 0; nt < 4; ++nt)
#pragma unroll
            for (int r = 0; r < 4; ++r) acc[mt][nt][r] = 0.0f;

    int tl = lane >> 3;
    int a_roff = (lane & 7) + (tl & 1) * 8;
    int a_coff = (tl >> 1) * 8;
    int b_roff = lane & 7;
    int b_coff = ((lane >> 3) & 1) * 8;

    uint32_t aBase[2];
#pragma unroll
    for (int mt = 0; mt < 2; ++mt) {
        int px = mw * 32 + mt * 16 + a_roff;
        int pr = px >> 5, pc = px & 31;
        aBase[mt] = sb + (uint32_t)(pr * 38 + pc) * ASTRIDE + (uint32_t)a_coff * 2;
    }
    uint32_t bBase = (uint32_t)(nw * 32 + b_roff) * ASTRIDE + (uint32_t)b_coff * 2;

    int b_co0 = tid >> 3, b_f4 = tid & 7;

    const float* inb = g_avg + (size_t)b * CC * HW;

    // ---- build A_ext once: 380 ext px x 64 ci, fp16 ----
#pragma unroll 4
    for (int it = 0; it < 96; ++it) {
        int idx = tid + it * 256;                 // 0..24575 = 64 ci * 384 slots
        int ci = idx / 384, p = idx - ci * 384;
        if (p < 380) {
            int er = p / 38, ec = p - er * 38;
            int gh = h0 - 3 + er, gw = w0 - 3 + ec;
            float v = 0.0f;
            if (gh >= 0 && gh < HH && gw >= 0 && gw < WW) v = inb[(size_t)ci * HW + gh * WW + gw];
            *(unsigned short*)(smem + p * ASTRIDE + ci * 2) =
                __half_as_ushort(__float2half_rn(v));
        }
    }
    // ---- stage B taps 0,1 into buffer 0 ----
    {
        const float4* s0 = (const float4*)(g_wt);
        const float4* s1 = (const float4*)(g_wt + (size_t)1 * (CC * CC));
        float4* d0 = (float4*)(smem + BS_OFF(0));
        float4* d1 = (float4*)(smem + BS_OFF(0) + 9216);
        d0[b_co0 * 9 + b_f4] = s0[tid];
        d0[(b_co0 + 32) * 9 + b_f4] = s0[tid + 256];
        d1[b_co0 * 9 + b_f4] = s1[tid];
        d1[(b_co0 + 32) * 9 + b_f4] = s1[tid + 256];
    }
    __syncthreads();

    for (int s = 0; s < 25; ++s) {
        int buf = s & 1;
        bool have_next = (s + 1 < 25);
        float4 v00, v01, v10, v11;
        if (have_next) {
            const float4* s0 = (const float4*)(g_wt + (size_t)(2 * s + 2) * (CC * CC));
            const float4* s1 = (const float4*)(g_wt + (size_t)(2 * s + 3) * (CC * CC));
            v00 = s0[tid]; v01 = s0[tid + 256];
            v10 = s1[tid]; v11 = s1[tid + 256];
        }

#pragma unroll
        for (int ti = 0; ti < 2; ++ti) {
            int t = 2 * s + ti;
            int toff = (t < 49) ? ((t / 7) * 38 + (t % 7)) * ASTRIDE : 0;  // pad tap: w=0
            uint32_t bptr = sb + BS_OFF(buf) + (uint32_t)ti * 9216 + bBase;
#pragma unroll
            for (int j = 0; j < 4; ++j) {
                uint32_t Ah[2][4];
#pragma unroll
                for (int mt = 0; mt < 2; ++mt)
                    LDMATRIX_X4(Ah[mt], aBase[mt] + (uint32_t)toff + (uint32_t)j * 32);
#pragma unroll
                for (int nt = 0; nt < 4; ++nt) {
                    uint32_t Bf[2];
                    LDMATRIX_X2(Bf, bptr + (uint32_t)(nt * 8) * ASTRIDE + (uint32_t)j * 32);
#pragma unroll
                    for (int mt = 0; mt < 2; ++mt)
                        MMA_F16(acc[mt][nt], Ah[mt], Bf);
                }
            }
        }

        if (have_next) {
            int nb = buf ^ 1;
            float4* d0 = (float4*)(smem + BS_OFF(nb));
            float4* d1 = (float4*)(smem + BS_OFF(nb) + 9216);
            d0[b_co0 * 9 + b_f4] = v00;
            d0[(b_co0 + 32) * 9 + b_f4] = v01;
            d1[b_co0 * 9 + b_f4] = v10;
            d1[(b_co0 + 32) * 9 + b_f4] = v11;
        }
        __syncthreads();
    }

    // ---- epilogue ----
    int g = lane >> 2, tig = lane & 3;
    float* o = out + (size_t)b * CC * HW;
#pragma unroll
    for (int mt = 0; mt < 2; ++mt) {
        int r0 = mw * 32 + mt * 16 + g;
        int oh0 = h0 + (r0 >> 5), ow0 = w0 + (r0 & 31);
        int r1 = r0 + 8;
        int oh1 = h0 + (r1 >> 5), ow1 = w0 + (r1 & 31);
#pragma unroll
        for (int nt = 0; nt < 4; ++nt) {
            int co = nw * 32 + nt * 8 + tig * 2;
            float bv0 = __ldg(&bias[co]), bv1 = __ldg(&bias[co + 1]);
            o[(size_t)co * HW + oh0 * WW + ow0] = acc[mt][nt][0] + bv0;
            o[(size_t)(co + 1) * HW + oh0 * WW + ow0] = acc[mt][nt][1] + bv1;
            o[(size_t)co * HW + oh1 * WW + ow1] = acc[mt][nt][2] + bv0;
            o[(size_t)(co + 1) * HW + oh1 * WW + ow1] = acc[mt][nt][3] + bv1;
        }
    }
}

// ============================================================
// Launch: two per-batch chains forked onto a second stream via events
// (legal graph-capture fork/join). Streams/events created once on the
// first (uncaptured) call; on failure fall back to single-stream = R8.
// ============================================================
extern "C" void kernel_launch(void* const* d_in, const int* in_sizes, int n_in,
                              void* d_out, int out_size) {
    const float* x   = (const float*)d_in[0];  // (10,64,100,352)
    const float* psm = (const float*)d_in[1];  // (10,2,100,352)
    // d_in[2] record_len: unused
    const float* pt  = (const float*)d_in[3];  // (2,5,5,4,4)
    const float* fw  = (const float*)d_in[4];  // (64,64,7,7)
    const float* fb  = (const float*)d_in[5];  // (64,)
    float* out = (float*)d_out;                // (2,64,100,352)

    static bool inited = false;
    static cudaStream_t sB = 0;
    static cudaEvent_t evF0 = 0, evP = 0, evJ1 = 0;
    if (!inited) {
        cudaFuncSetAttribute(k_conv_mma, cudaFuncAttributeMaxDynamicSharedMemorySize, SMEM_TC);
        if (cudaStreamCreateWithFlags(&sB, cudaStreamNonBlocking) != cudaSuccess) sB = 0;
        if (sB) {
            if (cudaEventCreateWithFlags(&evF0, cudaEventDisableTiming) != cudaSuccess ||
                cudaEventCreateWithFlags(&evP, cudaEventDisableTiming) != cudaSuccess ||
                cudaEventCreateWithFlags(&evJ1, cudaEventDisableTiming) != cudaSuccess) {
                sB = 0;  // fall back to single stream
            }
        }
        inited = true;
    }

    if (sB) {
        // fork: sB depends on start of main stream
        cudaEventRecord(evF0, 0);
        cudaStreamWaitEvent(sB, evF0, 0);

        // stream sB: batch 1 chain (+ weight prep, consumed by both convs)
        k_prepw<<<50, 256, 0, sB>>>(fw);
        cudaEventRecord(evP, sB);
        k_confwarp<<<dim3(HH, LL), WW, 0, sB>>>(psm, pt, LL);   // samples 5..9
        k_select<<<LL, 1024, 0, sB>>>(LL);
        k_warpacc<<<dim3(HH, 4, 1), WW, 0, sB>>>(x, pt, 1);
        k_conv_mma<<<dim3(WW / 32, HH / 4, 1), 256, SMEM_TC, sB>>>(out, fb, 1);
        cudaEventRecord(evJ1, sB);

        // stream 0: batch 0 chain
        k_confwarp<<<dim3(HH, LL), WW>>>(psm, pt, 0);           // samples 0..4
        k_select<<<LL, 1024>>>(0);
        k_warpacc<<<dim3(HH, 4, 1), WW>>>(x, pt, 0);
        cudaStreamWaitEvent(0, evP, 0);                          // conv0 needs weights
        k_conv_mma<<<dim3(WW / 32, HH / 4, 1), 256, SMEM_TC>>>(out, fb, 0);

        // join
        cudaStreamWaitEvent(0, evJ1, 0);
    } else {
        // fallback: exact R8 single-stream sequence
        k_prepw<<<50, 256>>>(fw);
        k_confwarp<<<dim3(HH, LL), WW>>>(psm, pt, 0);
        k_confwarp<<<dim3(HH, LL), WW>>>(psm, pt, LL);
        k_select<<<LL, 1024>>>(0);
        k_select<<<LL, 1024>>>(LL);
        k_warpacc<<<dim3(HH, 4, 1), WW>>>(x, pt, 0);
        k_warpacc<<<dim3(HH, 4, 1), WW>>>(x, pt, 1);
        k_conv_mma<<<dim3(WW / 32, HH / 4, 1), 256, SMEM_TC>>>(out, fb, 0);
        k_conv_mma<<<dim3(WW / 32, HH / 4, 1), 256, SMEM_TC>>>(out, fb, 1);
    }
}

// round 14
// speedup vs baseline: 1.2068x; 1.0925x over previous
#include <cuda_runtime.h>
#include <cuda_fp16.h>
#include <math.h>
#include <stdint.h>

#define NIMG 10
#define BB 2
#define LL 5
#define CC 64
#define HH 100
#define WW 352
#define HW 35200
#define KSEL 8800

// ---- scratch (static device globals; no allocation) ----
__device__ float g_conf[NIMG * HW];    // sigmoid(max psm) map (bit-exact vs XLA)
__device__ float g_confw[NIMG * HW];   // warped confidence (bit-exact vs XLA)
__device__ float g_thr[NIMG];          // per-sample K-th largest conf value
__device__ float g_avg[BB * CC * HW];  // (1/L) * sum_l sparse_l, per batch
// conv weights per tap, fp16: [t][co][ci], padded to 50 taps (tap 49 = 0)
__device__ unsigned short g_wt[50 * CC * CC];

// scale constants, computed in double then rounded to f32 (matches Python)
#define S01 ((float)(100.0 / 352.0))
#define S02 ((float)(2.0 / (2.0 * 0.4 * 352.0)))
#define S10 ((float)(352.0 / 100.0))
#define S12 ((float)(2.0 / (2.0 * 0.4 * 100.0)))
#define CXW ((float)(2.0 / 352.0))
#define CYH ((float)(2.0 / 100.0))

// ============================================================
// mma.sync / ldmatrix helpers (baseline PTX, sm_80+; OK on sm_103 plain)
// ============================================================
static __device__ __forceinline__ uint32_t smem_u32(const void* p) {
    uint32_t a;
    asm("{ .reg .u64 t; cvta.to.shared.u64 t, %1; cvt.u32.u64 %0, t; }" : "=r"(a) : "l"(p));
    return a;
}

#define LDMATRIX_X4(r, addr) \
    asm volatile("ldmatrix.sync.aligned.m8n8.x4.shared.b16 {%0,%1,%2,%3}, [%4];" \
        : "=r"((r)[0]), "=r"((r)[1]), "=r"((r)[2]), "=r"((r)[3]) : "r"(addr))

#define LDMATRIX_X2(r, addr) \
    asm volatile("ldmatrix.sync.aligned.m8n8.x2.shared.b16 {%0,%1}, [%2];" \
        : "=r"((r)[0]), "=r"((r)[1]) : "r"(addr))

#define MMA_F16(d, a, bfr) \
    asm volatile("mma.sync.aligned.m16n8k16.row.col.f32.f16.f16.f32 " \
        "{%0,%1,%2,%3}, {%4,%5,%6,%7}, {%8,%9}, {%0,%1,%2,%3};" \
        : "+f"((d)[0]), "+f"((d)[1]), "+f"((d)[2]), "+f"((d)[3]) \
        : "r"((a)[0]), "r"((a)[1]), "r"((a)[2]), "r"((a)[3]), "r"((bfr)[0]), "r"((bfr)[1]))

// ---- XLA f32 tanh (Eigen-style rational approx, uncontracted mul/add) ----
__device__ __forceinline__ float xla_tanh(float x) {
    float cx = fminf(fmaxf(x, -7.90531110763549805f), 7.90531110763549805f);
    float x2 = __fmul_rn(cx, cx);
    float p = -2.76076847742355e-16f;
    p = __fadd_rn(__fmul_rn(p, x2), 2.00018790482477e-13f);
    p = __fadd_rn(__fmul_rn(p, x2), -8.60467152213735e-11f);
    p = __fadd_rn(__fmul_rn(p, x2), 5.12229709037114e-08f);
    p = __fadd_rn(__fmul_rn(p, x2), 1.48572235717979e-05f);
    p = __fadd_rn(__fmul_rn(p, x2), 6.37261928875436e-04f);
    p = __fadd_rn(__fmul_rn(p, x2), 4.89352455891786e-03f);
    float num = __fmul_rn(cx, p);
    float q = 1.19825839466702e-06f;
    q = __fadd_rn(__fmul_rn(q, x2), 1.18534705686654e-04f);
    q = __fadd_rn(__fmul_rn(q, x2), 2.26843463243900e-03f);
    q = __fadd_rn(__fmul_rn(q, x2), 4.89352518554385e-03f);
    float r = __fdiv_rn(num, q);
    return (fabsf(x) < 0.0004f) ? x : r;
}
__device__ __forceinline__ float xla_sigmoid(float x) {
    return __fadd_rn(0.5f, __fmul_rn(0.5f, xla_tanh(__fmul_rn(0.5f, x))));
}

__device__ __forceinline__ void get_theta(const float* __restrict__ pt, int b, int l, float th[6]) {
    const float* p = pt + b * (LL * LL * 16) + l * 16;
    th[0] = p[0];
    th[1] = p[1] * S01;
    th[2] = p[3] * S02;
    th[3] = p[4] * S10;
    th[4] = p[5];
    th[5] = p[7] * S12;
}

// ============================================================
// Kernel 0: conf map = sigmoid(max(psm over 2 ch)), elementwise, strict XLA.
// Covers LL samples starting at `base`.
// ============================================================
__global__ __launch_bounds__(256) void k_conf(const float* __restrict__ psm, int base) {
    int i = blockIdx.x * 256 + threadIdx.x;
    if (i < LL * HW) {
        int n = base + i / HW, hw = i - (i / HW) * HW;
        const float* bp = psm + (size_t)n * 2 * HW;
        float m = fmaxf(bp[hw], bp[HW + hw]);
        g_conf[(size_t)n * HW + hw] = xla_sigmoid(m);
    }
}

// ============================================================
// Kernel 1: warp conf map (gather-only; strict fp32 sequence; bit-exact:
// gathered values identical to per-corner sigmoid eval). grid (H, LL)/batch.
// ============================================================
__global__ __launch_bounds__(WW) void k_confwarp(const float* __restrict__ pt, int base) {
    int h = blockIdx.x, n = base + blockIdx.y, w = threadIdx.x;
    int b = n / LL, l = n % LL;
    const float* p = pt + b * (LL * LL * 16) + l * 16;
    float th0 = p[0];
    float th1 = __fmul_rn(p[1], S01);
    float th2 = __fmul_rn(p[3], S02);
    float th3 = __fmul_rn(p[4], S10);
    float th4 = p[5];
    float th5 = __fmul_rn(p[7], S12);

    float gx = __fsub_rn(__fmul_rn(__fadd_rn((float)w, 0.5f), CXW), 1.0f);
    float gy = __fsub_rn(__fmul_rn(__fadd_rn((float)h, 0.5f), CYH), 1.0f);
    float src_x = __fadd_rn(__fadd_rn(__fmul_rn(th0, gx), __fmul_rn(th1, gy)), th2);
    float src_y = __fadd_rn(__fadd_rn(__fmul_rn(th3, gx), __fmul_rn(th4, gy)), th5);
    float px = __fsub_rn(__fmul_rn(__fadd_rn(src_x, 1.0f), 176.0f), 0.5f);
    float py = __fsub_rn(__fmul_rn(__fadd_rn(src_y, 1.0f), 50.0f), 0.5f);
    float x0 = floorf(px), y0 = floorf(py);
    float wx1 = __fsub_rn(px, x0), wx0 = __fsub_rn(1.0f, wx1);
    float wy1 = __fsub_rn(py, y0), wy0 = __fsub_rn(1.0f, wy1);

    const float* cmap = g_conf + (size_t)n * HW;
    float acc = 0.0f;
#pragma unroll
    for (int dy = 0; dy < 2; ++dy) {
#pragma unroll
        for (int dx = 0; dx < 2; ++dx) {
            float yy = dy ? __fadd_rn(y0, 1.0f) : y0;
            float xx = dx ? __fadd_rn(x0, 1.0f) : x0;
            if (yy >= 0.0f && yy <= (float)(HH - 1) && xx >= 0.0f && xx <= (float)(WW - 1)) {
                int yi = (int)yy, xi = (int)xx;
                float s = cmap[yi * WW + xi];
                float wgt = __fmul_rn(dy ? wy1 : wy0, dx ? wx1 : wx0);
                acc = __fadd_rn(acc, __fmul_rn(s, wgt));
            }
        }
    }
    g_confw[n * HW + h * WW + w] = acc;
}

// ============================================================
// Kernel 2: K-th largest via 4x8-bit MSB radix select (proven structure).
// New: unroll-4 batched loads (MLP) + parallel suffix-scan bin selection
// (identical semantics to the serial top-down scan). grid LL per batch.
// ============================================================
__global__ __launch_bounds__(1024) void k_select(int base) {
    int n = base + blockIdx.x;
    const float* v = g_confw + (size_t)n * HW;
    __shared__ unsigned int hist[256];
    __shared__ unsigned int sfx[256];
    __shared__ unsigned int s_prefix, s_krem;
    int tid = threadIdx.x;
    if (tid == 0) { s_prefix = 0u; s_krem = KSEL; }
    __syncthreads();
    for (int pass = 0; pass < 4; ++pass) {
        int shift = 24 - pass * 8;
        unsigned int pmask = (pass == 0) ? 0u : (0xFFFFFFFFu << (shift + 8));
        if (tid < 256) hist[tid] = 0u;
        __syncthreads();
        unsigned int prefix = s_prefix;
        // 35200 = 8*4096 + 2*1024 + 384 ; batched loads for MLP
#pragma unroll 2
        for (int it = 0; it < 8; ++it) {
            int i = it * 4096 + tid;
            unsigned int k0 = __float_as_uint(v[i]);
            unsigned int k1 = __float_as_uint(v[i + 1024]);
            unsigned int k2 = __float_as_uint(v[i + 2048]);
            unsigned int k3 = __float_as_uint(v[i + 3072]);
            if ((k0 & pmask) == prefix) atomicAdd(&hist[(k0 >> shift) & 255u], 1u);
            if ((k1 & pmask) == prefix) atomicAdd(&hist[(k1 >> shift) & 255u], 1u);
            if ((k2 & pmask) == prefix) atomicAdd(&hist[(k2 >> shift) & 255u], 1u);
            if ((k3 & pmask) == prefix) atomicAdd(&hist[(k3 >> shift) & 255u], 1u);
        }
        {
            unsigned int k0 = __float_as_uint(v[32768 + tid]);
            unsigned int k1 = __float_as_uint(v[33792 + tid]);
            unsigned int k2 = (tid < 384) ? __float_as_uint(v[34816 + tid]) : 0u;
            if ((k0 & pmask) == prefix) atomicAdd(&hist[(k0 >> shift) & 255u], 1u);
            if ((k1 & pmask) == prefix) atomicAdd(&hist[(k1 >> shift) & 255u], 1u);
            if (tid < 384 && (k2 & pmask) == prefix) atomicAdd(&hist[(k2 >> shift) & 255u], 1u);
        }
        __syncthreads();
        // parallel suffix sums: sfx[b] = sum_{j>=b} hist[j]
        if (tid < 256) sfx[tid] = hist[tid];
        __syncthreads();
#pragma unroll
        for (int off = 1; off < 256; off <<= 1) {
            unsigned int add = (tid < 256 && tid + off < 256) ? sfx[tid + off] : 0u;
            __syncthreads();
            if (tid < 256) sfx[tid] += add;
            __syncthreads();
        }
        // unique b: S[b] >= krem > S[b+1]  (== serial top-down scan result)
        unsigned int krem = s_krem;
        if (tid < 256) {
            unsigned int S = sfx[tid];
            unsigned int Sn = (tid == 255) ? 0u : sfx[tid + 1];
            if (S >= krem && Sn < krem) {
                s_prefix = prefix | ((unsigned int)tid << shift);
                s_krem = krem - Sn;
            }
        }
        __syncthreads();
    }
    if (tid == 0) g_thr[n] = __uint_as_float(s_prefix);
}

// ============================================================
// Kernel 3 (R8 exact): warp x + mask + (1/L)-accumulate over l.
// grid (H, 4, 1) per batch.
// ============================================================
__global__ __launch_bounds__(WW) void k_warpacc(const float* __restrict__ x,
                                                const float* __restrict__ pt, int b) {
    int h = blockIdx.x, cg = blockIdx.y, w = threadIdx.x;
    float acc[16];
#pragma unroll
    for (int i = 0; i < 16; ++i) acc[i] = 0.0f;
    float gx = (w + 0.5f) * (2.0f / WW) - 1.0f;
    float gy = (h + 0.5f) * (2.0f / HH) - 1.0f;
    for (int l = 0; l < LL; ++l) {
        int n = b * LL + l;
        if (l != 0 && g_confw[n * HW + h * WW + w] < g_thr[n]) continue;
        float th[6];
        get_theta(pt, b, l, th);
        float px = (th[0] * gx + th[1] * gy + th[2] + 1.0f) * (WW * 0.5f) - 0.5f;
        float py = (th[3] * gx + th[4] * gy + th[5] + 1.0f) * (HH * 0.5f) - 0.5f;
        float x0 = floorf(px), y0 = floorf(py);
        float wx1 = px - x0, wx0 = 1.0f - wx1;
        float wy1 = py - y0, wy0 = 1.0f - wy1;
        bool vx0 = (x0 >= 0.0f) && (x0 <= (float)(WW - 1));
        bool vx1 = (x0 + 1.0f >= 0.0f) && (x0 + 1.0f <= (float)(WW - 1));
        bool vy0 = (y0 >= 0.0f) && (y0 <= (float)(HH - 1));
        bool vy1 = (y0 + 1.0f >= 0.0f) && (y0 + 1.0f <= (float)(HH - 1));
        int x0i = (int)fminf(fmaxf(x0, 0.0f), (float)(WW - 1));
        int x1i = (int)fminf(fmaxf(x0 + 1.0f, 0.0f), (float)(WW - 1));
        int y0i = (int)fminf(fmaxf(y0, 0.0f), (float)(HH - 1));
        int y1i = (int)fminf(fmaxf(y0 + 1.0f, 0.0f), (float)(HH - 1));
        float m00 = (vy0 && vx0) ? wy0 * wx0 * 0.2f : 0.0f;
        float m01 = (vy0 && vx1) ? wy0 * wx1 * 0.2f : 0.0f;
        float m10 = (vy1 && vx0) ? wy1 * wx0 * 0.2f : 0.0f;
        float m11 = (vy1 && vx1) ? wy1 * wx1 * 0.2f : 0.0f;
        int i00 = y0i * WW + x0i, i01 = y0i * WW + x1i;
        int i10 = y1i * WW + x0i, i11 = y1i * WW + x1i;
        const float* xb = x + (size_t)(n * CC + cg * 16) * HW;
#pragma unroll
        for (int c = 0; c < 16; ++c) {
            const float* xc = xb + c * HW;
            acc[c] += xc[i00] * m00 + xc[i01] * m01 + xc[i10] * m10 + xc[i11] * m11;
        }
    }
    int outbase = ((b * CC + cg * 16) * HH + h) * WW + w;
#pragma unroll
    for (int c = 0; c < 16; ++c) g_avg[outbase + c * HW] = acc[c];
}

// ============================================================
// Kernel 3b (R8 exact): weights -> fp16 per tap. grid 50 (tap 49 = 0).
// ============================================================
__global__ __launch_bounds__(256) void k_prepw(const float* __restrict__ fw) {
    int t = blockIdx.x;
    for (int e = threadIdx.x; e < CC * CC; e += 256) {
        int co = e >> 6, ci = e & 63;
        float v = (t < 49) ? fw[(size_t)(co * CC + ci) * 49 + t] : 0.0f;
        g_wt[(size_t)t * (CC * CC) + e] = __half_as_ushort(__float2half_rn(v));
    }
}

// ============================================================
// Kernel 4 (R8 exact): 7x7 conv via mma.sync implicit GEMM, taps-outer.
// Single-pass fp16, 25 two-tap stages, 2 blocks/SM. grid (11, 25, 1)/batch.
// ============================================================
#define ASTRIDE 144
#define AS_SZ 54720                       // 380 * 144
#define BS_OFF(buf) (AS_SZ + (buf) * 18432)
#define SMEM_TC 91584

__global__ void __launch_bounds__(256, 2) k_conv_mma(float* __restrict__ out,
                                                     const float* __restrict__ bias, int b) {
    extern __shared__ unsigned char smem[];
    uint32_t sb = smem_u32(smem);
    int tid = threadIdx.x;
    int lane = tid & 31, wrp = tid >> 5;
    int mw = wrp & 3, nw = wrp >> 2;
    int h0 = blockIdx.y * 4, w0 = blockIdx.x * 32;

    float acc[2][4][4];
#pragma unroll
    for (int mt = 0; mt < 2; ++mt)
#pragma unroll
        for (int nt = 0; nt < 4; ++nt)
#pragma unroll
            for (int r = 0; r < 4; ++r) acc[mt][nt][r] = 0.0f;

    int tl = lane >> 3;
    int a_roff = (lane & 7) + (tl & 1) * 8;
    int a_coff = (tl >> 1) * 8;
    int b_roff = lane & 7;
    int b_coff = ((lane >> 3) & 1) * 8;

    uint32_t aBase[2];
#pragma unroll
    for (int mt = 0; mt < 2; ++mt) {
        int px = mw * 32 + mt * 16 + a_roff;
        int pr = px >> 5, pc = px & 31;
        aBase[mt] = sb + (uint32_t)(pr * 38 + pc) * ASTRIDE + (uint32_t)a_coff * 2;
    }
    uint32_t bBase = (uint32_t)(nw * 32 + b_roff) * ASTRIDE + (uint32_t)b_coff * 2;

    int b_co0 = tid >> 3, b_f4 = tid & 7;

    const float* inb = g_avg + (size_t)b * CC * HW;

    // ---- build A_ext once: 380 ext px x 64 ci, fp16 ----
#pragma unroll 4
    for (int it = 0; it < 96; ++it) {
        int idx = tid + it * 256;                 // 0..24575 = 64 ci * 384 slots
        int ci = idx / 384, p = idx - ci * 384;
        if (p < 380) {
            int er = p / 38, ec = p - er * 38;
            int gh = h0 - 3 + er, gw = w0 - 3 + ec;
            float v = 0.0f;
            if (gh >= 0 && gh < HH && gw >= 0 && gw < WW) v = inb[(size_t)ci * HW + gh * WW + gw];
            *(unsigned short*)(smem + p * ASTRIDE + ci * 2) =
                __half_as_ushort(__float2half_rn(v));
        }
    }
    // ---- stage B taps 0,1 into buffer 0 ----
    {
        const float4* s0 = (const float4*)(g_wt);
        const float4* s1 = (const float4*)(g_wt + (size_t)1 * (CC * CC));
        float4* d0 = (float4*)(smem + BS_OFF(0));
        float4* d1 = (float4*)(smem + BS_OFF(0) + 9216);
        d0[b_co0 * 9 + b_f4] = s0[tid];
        d0[(b_co0 + 32) * 9 + b_f4] = s0[tid + 256];
        d1[b_co0 * 9 + b_f4] = s1[tid];
        d1[(b_co0 + 32) * 9 + b_f4] = s1[tid + 256];
    }
    __syncthreads();

    for (int s = 0; s < 25; ++s) {
        int buf = s & 1;
        bool have_next = (s + 1 < 25);
        float4 v00, v01, v10, v11;
        if (have_next) {
            const float4* s0 = (const float4*)(g_wt + (size_t)(2 * s + 2) * (CC * CC));
            const float4* s1 = (const float4*)(g_wt + (size_t)(2 * s + 3) * (CC * CC));
            v00 = s0[tid]; v01 = s0[tid + 256];
            v10 = s1[tid]; v11 = s1[tid + 256];
        }

#pragma unroll
        for (int ti = 0; ti < 2; ++ti) {
            int t = 2 * s + ti;
            int toff = (t < 49) ? ((t / 7) * 38 + (t % 7)) * ASTRIDE : 0;  // pad tap: w=0
            uint32_t bptr = sb + BS_OFF(buf) + (uint32_t)ti * 9216 + bBase;
#pragma unroll
            for (int j = 0; j < 4; ++j) {
                uint32_t Ah[2][4];
#pragma unroll
                for (int mt = 0; mt < 2; ++mt)
                    LDMATRIX_X4(Ah[mt], aBase[mt] + (uint32_t)toff + (uint32_t)j * 32);
#pragma unroll
                for (int nt = 0; nt < 4; ++nt) {
                    uint32_t Bf[2];
                    LDMATRIX_X2(Bf, bptr + (uint32_t)(nt * 8) * ASTRIDE + (uint32_t)j * 32);
#pragma unroll
                    for (int mt = 0; mt < 2; ++mt)
                        MMA_F16(acc[mt][nt], Ah[mt], Bf);
                }
            }
        }

        if (have_next) {
            int nb = buf ^ 1;
            float4* d0 = (float4*)(smem + BS_OFF(nb));
            float4* d1 = (float4*)(smem + BS_OFF(nb) + 9216);
            d0[b_co0 * 9 + b_f4] = v00;
            d0[(b_co0 + 32) * 9 + b_f4] = v01;
            d1[b_co0 * 9 + b_f4] = v10;
            d1[(b_co0 + 32) * 9 + b_f4] = v11;
        }
        __syncthreads();
    }

    // ---- epilogue ----
    int g = lane >> 2, tig = lane & 3;
    float* o = out + (size_t)b * CC * HW;
#pragma unroll
    for (int mt = 0; mt < 2; ++mt) {
        int r0 = mw * 32 + mt * 16 + g;
        int oh0 = h0 + (r0 >> 5), ow0 = w0 + (r0 & 31);
        int r1 = r0 + 8;
        int oh1 = h0 + (r1 >> 5), ow1 = w0 + (r1 & 31);
#pragma unroll
        for (int nt = 0; nt < 4; ++nt) {
            int co = nw * 32 + nt * 8 + tig * 2;
            float bv0 = __ldg(&bias[co]), bv1 = __ldg(&bias[co + 1]);
            o[(size_t)co * HW + oh0 * WW + ow0] = acc[mt][nt][0] + bv0;
            o[(size_t)(co + 1) * HW + oh0 * WW + ow0] = acc[mt][nt][1] + bv1;
            o[(size_t)co * HW + oh1 * WW + ow1] = acc[mt][nt][2] + bv0;
            o[(size_t)(co + 1) * HW + oh1 * WW + ow1] = acc[mt][nt][3] + bv1;
        }
    }
}

// ============================================================
// Launch: two per-batch chains forked onto a second stream via events.
// ============================================================
extern "C" void kernel_launch(void* const* d_in, const int* in_sizes, int n_in,
                              void* d_out, int out_size) {
    const float* x   = (const float*)d_in[0];  // (10,64,100,352)
    const float* psm = (const float*)d_in[1];  // (10,2,100,352)
    // d_in[2] record_len: unused
    const float* pt  = (const float*)d_in[3];  // (2,5,5,4,4)
    const float* fw  = (const float*)d_in[4];  // (64,64,7,7)
    const float* fb  = (const float*)d_in[5];  // (64,)
    float* out = (float*)d_out;                // (2,64,100,352)

    static bool inited = false;
    static cudaStream_t sB = 0;
    static cudaEvent_t evF0 = 0, evP = 0, evJ1 = 0;
    if (!inited) {
        cudaFuncSetAttribute(k_conv_mma, cudaFuncAttributeMaxDynamicSharedMemorySize, SMEM_TC);
        if (cudaStreamCreateWithFlags(&sB, cudaStreamNonBlocking) != cudaSuccess) sB = 0;
        if (sB) {
            if (cudaEventCreateWithFlags(&evF0, cudaEventDisableTiming) != cudaSuccess ||
                cudaEventCreateWithFlags(&evP, cudaEventDisableTiming) != cudaSuccess ||
                cudaEventCreateWithFlags(&evJ1, cudaEventDisableTiming) != cudaSuccess) {
                sB = 0;
            }
        }
        inited = true;
    }

    const int nconf = (LL * HW + 255) / 256;

    if (sB) {
        cudaEventRecord(evF0, 0);
        cudaStreamWaitEvent(sB, evF0, 0);

        // stream sB: batch 1 chain (+ weight prep, consumed by both convs)
        k_prepw<<<50, 256, 0, sB>>>(fw);
        cudaEventRecord(evP, sB);
        k_conf<<<nconf, 256, 0, sB>>>(psm, LL);
        k_confwarp<<<dim3(HH, LL), WW, 0, sB>>>(pt, LL);
        k_select<<<LL, 1024, 0, sB>>>(LL);
        k_warpacc<<<dim3(HH, 4, 1), WW, 0, sB>>>(x, pt, 1);
        k_conv_mma<<<dim3(WW / 32, HH / 4, 1), 256, SMEM_TC, sB>>>(out, fb, 1);
        cudaEventRecord(evJ1, sB);

        // stream 0: batch 0 chain
        k_conf<<<nconf, 256>>>(psm, 0);
        k_confwarp<<<dim3(HH, LL), WW>>>(pt, 0);
        k_select<<<LL, 1024>>>(0);
        k_warpacc<<<dim3(HH, 4, 1), WW>>>(x, pt, 0);
        cudaStreamWaitEvent(0, evP, 0);
        k_conv_mma<<<dim3(WW / 32, HH / 4, 1), 256, SMEM_TC>>>(out, fb, 0);

        cudaStreamWaitEvent(0, evJ1, 0);
    } else {
        // fallback: single-stream sequence
        k_prepw<<<50, 256>>>(fw);
        k_conf<<<nconf, 256>>>(psm, 0);
        k_conf<<<nconf, 256>>>(psm, LL);
        k_confwarp<<<dim3(HH, LL), WW>>>(pt, 0);
        k_confwarp<<<dim3(HH, LL), WW>>>(pt, LL);
        k_select<<<LL, 1024>>>(0);
        k_select<<<LL, 1024>>>(LL);
        k_warpacc<<<dim3(HH, 4, 1), WW>>>(x, pt, 0);
        k_warpacc<<<dim3(HH, 4, 1), WW>>>(x, pt, 1);
        k_conv_mma<<<dim3(WW / 32, HH / 4, 1), 256, SMEM_TC>>>(out, fb, 0);
        k_conv_mma<<<dim3(WW / 32, HH / 4, 1), 256, SMEM_TC>>>(out, fb, 1);
    }
}

// round 15
// speedup vs baseline: 1.2323x; 1.0211x over previous
#include <cuda_runtime.h>
#include <cuda_fp16.h>
#include <math.h>
#include <stdint.h>

#define NIMG 10
#define BB 2
#define LL 5
#define CC 64
#define HH 100
#define WW 352
#define HW 35200
#define KSEL 8800

// ---- scratch (static device globals; no allocation) ----
__device__ float g_conf[NIMG * HW];    // sigmoid(max psm) map (bit-exact vs XLA)
__device__ float g_confw[NIMG * HW];   // warped confidence (bit-exact vs XLA)
__device__ float g_thr[NIMG];          // per-sample K-th largest conf value
__device__ float g_avg[BB * CC * HW];  // (1/L) * sum_l sparse_l, per batch
// conv weights per tap, fp16: [t][co][ci], padded to 50 taps (tap 49 = 0)
__device__ unsigned short g_wt[50 * CC * CC];

// scale constants, computed in double then rounded to f32 (matches Python)
#define S01 ((float)(100.0 / 352.0))
#define S02 ((float)(2.0 / (2.0 * 0.4 * 352.0)))
#define S10 ((float)(352.0 / 100.0))
#define S12 ((float)(2.0 / (2.0 * 0.4 * 100.0)))
#define CXW ((float)(2.0 / 352.0))
#define CYH ((float)(2.0 / 100.0))

// ============================================================
// mma.sync / ldmatrix helpers (baseline PTX, sm_80+; OK on sm_103 plain)
// ============================================================
static __device__ __forceinline__ uint32_t smem_u32(const void* p) {
    uint32_t a;
    asm("{ .reg .u64 t; cvta.to.shared.u64 t, %1; cvt.u32.u64 %0, t; }" : "=r"(a) : "l"(p));
    return a;
}

#define LDMATRIX_X4(r, addr) \
    asm volatile("ldmatrix.sync.aligned.m8n8.x4.shared.b16 {%0,%1,%2,%3}, [%4];" \
        : "=r"((r)[0]), "=r"((r)[1]), "=r"((r)[2]), "=r"((r)[3]) : "r"(addr))

#define LDMATRIX_X2(r, addr) \
    asm volatile("ldmatrix.sync.aligned.m8n8.x2.shared.b16 {%0,%1}, [%2];" \
        : "=r"((r)[0]), "=r"((r)[1]) : "r"(addr))

#define MMA_F16(d, a, bfr) \
    asm volatile("mma.sync.aligned.m16n8k16.row.col.f32.f16.f16.f32 " \
        "{%0,%1,%2,%3}, {%4,%5,%6,%7}, {%8,%9}, {%0,%1,%2,%3};" \
        : "+f"((d)[0]), "+f"((d)[1]), "+f"((d)[2]), "+f"((d)[3]) \
        : "r"((a)[0]), "r"((a)[1]), "r"((a)[2]), "r"((a)[3]), "r"((bfr)[0]), "r"((bfr)[1]))

// ---- XLA f32 tanh (Eigen-style rational approx, uncontracted mul/add) ----
__device__ __forceinline__ float xla_tanh(float x) {
    float cx = fminf(fmaxf(x, -7.90531110763549805f), 7.90531110763549805f);
    float x2 = __fmul_rn(cx, cx);
    float p = -2.76076847742355e-16f;
    p = __fadd_rn(__fmul_rn(p, x2), 2.00018790482477e-13f);
    p = __fadd_rn(__fmul_rn(p, x2), -8.60467152213735e-11f);
    p = __fadd_rn(__fmul_rn(p, x2), 5.12229709037114e-08f);
    p = __fadd_rn(__fmul_rn(p, x2), 1.48572235717979e-05f);
    p = __fadd_rn(__fmul_rn(p, x2), 6.37261928875436e-04f);
    p = __fadd_rn(__fmul_rn(p, x2), 4.89352455891786e-03f);
    float num = __fmul_rn(cx, p);
    float q = 1.19825839466702e-06f;
    q = __fadd_rn(__fmul_rn(q, x2), 1.18534705686654e-04f);
    q = __fadd_rn(__fmul_rn(q, x2), 2.26843463243900e-03f);
    q = __fadd_rn(__fmul_rn(q, x2), 4.89352518554385e-03f);
    float r = __fdiv_rn(num, q);
    return (fabsf(x) < 0.0004f) ? x : r;
}
__device__ __forceinline__ float xla_sigmoid(float x) {
    return __fadd_rn(0.5f, __fmul_rn(0.5f, xla_tanh(__fmul_rn(0.5f, x))));
}

__device__ __forceinline__ void get_theta(const float* __restrict__ pt, int b, int l, float th[6]) {
    const float* p = pt + b * (LL * LL * 16) + l * 16;
    th[0] = p[0];
    th[1] = p[1] * S01;
    th[2] = p[3] * S02;
    th[3] = p[4] * S10;
    th[4] = p[5];
    th[5] = p[7] * S12;
}

// ============================================================
// Kernel 0: conf map = sigmoid(max(psm over 2 ch)), elementwise, strict XLA.
// ============================================================
__global__ __launch_bounds__(256) void k_conf(const float* __restrict__ psm, int base) {
    int i = blockIdx.x * 256 + threadIdx.x;
    if (i < LL * HW) {
        int n = base + i / HW, hw = i - (i / HW) * HW;
        const float* bp = psm + (size_t)n * 2 * HW;
        float m = fmaxf(bp[hw], bp[HW + hw]);
        g_conf[(size_t)n * HW + hw] = xla_sigmoid(m);
    }
}

// ============================================================
// Kernel 1: warp conf map (gather-only; strict fp32 sequence; bit-exact).
// grid (H, LL) per batch.
// ============================================================
__global__ __launch_bounds__(WW) void k_confwarp(const float* __restrict__ pt, int base) {
    int h = blockIdx.x, n = base + blockIdx.y, w = threadIdx.x;
    int b = n / LL, l = n % LL;
    const float* p = pt + b * (LL * LL * 16) + l * 16;
    float th0 = p[0];
    float th1 = __fmul_rn(p[1], S01);
    float th2 = __fmul_rn(p[3], S02);
    float th3 = __fmul_rn(p[4], S10);
    float th4 = p[5];
    float th5 = __fmul_rn(p[7], S12);

    float gx = __fsub_rn(__fmul_rn(__fadd_rn((float)w, 0.5f), CXW), 1.0f);
    float gy = __fsub_rn(__fmul_rn(__fadd_rn((float)h, 0.5f), CYH), 1.0f);
    float src_x = __fadd_rn(__fadd_rn(__fmul_rn(th0, gx), __fmul_rn(th1, gy)), th2);
    float src_y = __fadd_rn(__fadd_rn(__fmul_rn(th3, gx), __fmul_rn(th4, gy)), th5);
    float px = __fsub_rn(__fmul_rn(__fadd_rn(src_x, 1.0f), 176.0f), 0.5f);
    float py = __fsub_rn(__fmul_rn(__fadd_rn(src_y, 1.0f), 50.0f), 0.5f);
    float x0 = floorf(px), y0 = floorf(py);
    float wx1 = __fsub_rn(px, x0), wx0 = __fsub_rn(1.0f, wx1);
    float wy1 = __fsub_rn(py, y0), wy0 = __fsub_rn(1.0f, wy1);

    const float* cmap = g_conf + (size_t)n * HW;
    float acc = 0.0f;
#pragma unroll
    for (int dy = 0; dy < 2; ++dy) {
#pragma unroll
        for (int dx = 0; dx < 2; ++dx) {
            float yy = dy ? __fadd_rn(y0, 1.0f) : y0;
            float xx = dx ? __fadd_rn(x0, 1.0f) : x0;
            if (yy >= 0.0f && yy <= (float)(HH - 1) && xx >= 0.0f && xx <= (float)(WW - 1)) {
                int yi = (int)yy, xi = (int)xx;
                float s = cmap[yi * WW + xi];
                float wgt = __fmul_rn(dy ? wy1 : wy0, dx ? wx1 : wx0);
                acc = __fadd_rn(acc, __fmul_rn(s, wgt));
            }
        }
    }
    g_confw[n * HW + h * WW + w] = acc;
}

// ============================================================
// Kernel 2: K-th largest via 4x8-bit MSB radix select (R13 semantics).
// New: keys staged to dynamic shared in pass 0 (unroll-8 global loads);
// passes 1-3 scan shared (LDS). Parallel suffix-scan pick unchanged.
// ============================================================
#define SEL_SMEM (HW * 4)

__device__ __forceinline__ void sel_pick(unsigned int* hist, unsigned int* sfx,
                                         unsigned int* s_prefix, unsigned int* s_krem,
                                         unsigned int prefix, int shift, int tid) {
    if (tid < 256) sfx[tid] = hist[tid];
    __syncthreads();
#pragma unroll
    for (int off = 1; off < 256; off <<= 1) {
        unsigned int add = (tid < 256 && tid + off < 256) ? sfx[tid + off] : 0u;
        __syncthreads();
        if (tid < 256) sfx[tid] += add;
        __syncthreads();
    }
    unsigned int krem = *s_krem;
    if (tid < 256) {
        unsigned int S = sfx[tid];
        unsigned int Sn = (tid == 255) ? 0u : sfx[tid + 1];
        if (S >= krem && Sn < krem) {
            *s_prefix = prefix | ((unsigned int)tid << shift);
            *s_krem = krem - Sn;
        }
    }
    __syncthreads();
}

__global__ __launch_bounds__(1024) void k_select(int base) {
    extern __shared__ unsigned int keys[];   // HW staged keys
    __shared__ unsigned int hist[256];
    __shared__ unsigned int sfx[256];
    __shared__ unsigned int s_prefix, s_krem;
    int n = base + blockIdx.x;
    const unsigned int* v = (const unsigned int*)(g_confw + (size_t)n * HW);
    int tid = threadIdx.x;
    if (tid == 0) { s_prefix = 0u; s_krem = KSEL; }
    if (tid < 256) hist[tid] = 0u;
    __syncthreads();

    // ---- pass 0 (shift 24): global loads unroll-8, stage to shared, hist ----
    // 35200 = 4*8192 + 2*1024 + 384
#pragma unroll
    for (int bt = 0; bt < 4; ++bt) {
        int i0 = bt * 8192 + tid;
        unsigned int kk[8];
#pragma unroll
        for (int j = 0; j < 8; ++j) kk[j] = v[i0 + j * 1024];
#pragma unroll
        for (int j = 0; j < 8; ++j) {
            keys[i0 + j * 1024] = kk[j];
            atomicAdd(&hist[(kk[j] >> 24) & 255u], 1u);
        }
    }
    {
        unsigned int k0 = v[32768 + tid];
        unsigned int k1 = v[33792 + tid];
        unsigned int k2 = (tid < 384) ? v[34816 + tid] : 0u;
        keys[32768 + tid] = k0; atomicAdd(&hist[(k0 >> 24) & 255u], 1u);
        keys[33792 + tid] = k1; atomicAdd(&hist[(k1 >> 24) & 255u], 1u);
        if (tid < 384) { keys[34816 + tid] = k2; atomicAdd(&hist[(k2 >> 24) & 255u], 1u); }
    }
    __syncthreads();
    sel_pick(hist, sfx, &s_prefix, &s_krem, 0u, 24, tid);

    // ---- passes 1..3: scan staged keys in shared ----
    for (int pass = 1; pass < 4; ++pass) {
        int shift = 24 - pass * 8;
        unsigned int pmask = 0xFFFFFFFFu << (shift + 8);
        if (tid < 256) hist[tid] = 0u;
        __syncthreads();
        unsigned int prefix = s_prefix;
#pragma unroll 2
        for (int it = 0; it < 8; ++it) {
            int i = it * 4096 + tid;
            unsigned int k0 = keys[i];
            unsigned int k1 = keys[i + 1024];
            unsigned int k2 = keys[i + 2048];
            unsigned int k3 = keys[i + 3072];
            if ((k0 & pmask) == prefix) atomicAdd(&hist[(k0 >> shift) & 255u], 1u);
            if ((k1 & pmask) == prefix) atomicAdd(&hist[(k1 >> shift) & 255u], 1u);
            if ((k2 & pmask) == prefix) atomicAdd(&hist[(k2 >> shift) & 255u], 1u);
            if ((k3 & pmask) == prefix) atomicAdd(&hist[(k3 >> shift) & 255u], 1u);
        }
        {
            unsigned int k0 = keys[32768 + tid];
            unsigned int k1 = keys[33792 + tid];
            unsigned int k2 = (tid < 384) ? keys[34816 + tid] : 0u;
            if ((k0 & pmask) == prefix) atomicAdd(&hist[(k0 >> shift) & 255u], 1u);
            if ((k1 & pmask) == prefix) atomicAdd(&hist[(k1 >> shift) & 255u], 1u);
            if (tid < 384 && (k2 & pmask) == prefix) atomicAdd(&hist[(k2 >> shift) & 255u], 1u);
        }
        __syncthreads();
        sel_pick(hist, sfx, &s_prefix, &s_krem, s_prefix, shift, tid);
    }
    if (tid == 0) g_thr[n] = __uint_as_float(s_prefix);
}

// ============================================================
// Kernel 3: warp x + mask + (1/L)-accumulate over l. grid (H, 4, 1)/batch.
// New: batched prefetch of all 5 confw + 5 thr (removes 4 exposed L2 stalls).
// ============================================================
__global__ __launch_bounds__(WW) void k_warpacc(const float* __restrict__ x,
                                                const float* __restrict__ pt, int b) {
    int h = blockIdx.x, cg = blockIdx.y, w = threadIdx.x;
    float acc[16];
#pragma unroll
    for (int i = 0; i < 16; ++i) acc[i] = 0.0f;
    float gx = (w + 0.5f) * (2.0f / WW) - 1.0f;
    float gy = (h + 0.5f) * (2.0f / HH) - 1.0f;

    float cw[LL], tr[LL];
    int hw = h * WW + w;
#pragma unroll
    for (int l = 0; l < LL; ++l) {
        int n = b * LL + l;
        cw[l] = g_confw[(size_t)n * HW + hw];
        tr[l] = g_thr[n];
    }

    for (int l = 0; l < LL; ++l) {
        if (l != 0 && cw[l] < tr[l]) continue;
        float th[6];
        get_theta(pt, b, l, th);
        int n = b * LL + l;
        float px = (th[0] * gx + th[1] * gy + th[2] + 1.0f) * (WW * 0.5f) - 0.5f;
        float py = (th[3] * gx + th[4] * gy + th[5] + 1.0f) * (HH * 0.5f) - 0.5f;
        float x0 = floorf(px), y0 = floorf(py);
        float wx1 = px - x0, wx0 = 1.0f - wx1;
        float wy1 = py - y0, wy0 = 1.0f - wy1;
        bool vx0 = (x0 >= 0.0f) && (x0 <= (float)(WW - 1));
        bool vx1 = (x0 + 1.0f >= 0.0f) && (x0 + 1.0f <= (float)(WW - 1));
        bool vy0 = (y0 >= 0.0f) && (y0 <= (float)(HH - 1));
        bool vy1 = (y0 + 1.0f >= 0.0f) && (y0 + 1.0f <= (float)(HH - 1));
        int x0i = (int)fminf(fmaxf(x0, 0.0f), (float)(WW - 1));
        int x1i = (int)fminf(fmaxf(x0 + 1.0f, 0.0f), (float)(WW - 1));
        int y0i = (int)fminf(fmaxf(y0, 0.0f), (float)(HH - 1));
        int y1i = (int)fminf(fmaxf(y0 + 1.0f, 0.0f), (float)(HH - 1));
        float m00 = (vy0 && vx0) ? wy0 * wx0 * 0.2f : 0.0f;
        float m01 = (vy0 && vx1) ? wy0 * wx1 * 0.2f : 0.0f;
        float m10 = (vy1 && vx0) ? wy1 * wx0 * 0.2f : 0.0f;
        float m11 = (vy1 && vx1) ? wy1 * wx1 * 0.2f : 0.0f;
        int i00 = y0i * WW + x0i, i01 = y0i * WW + x1i;
        int i10 = y1i * WW + x0i, i11 = y1i * WW + x1i;
        const float* xb = x + (size_t)(n * CC + cg * 16) * HW;
#pragma unroll
        for (int c = 0; c < 16; ++c) {
            const float* xc = xb + c * HW;
            acc[c] += xc[i00] * m00 + xc[i01] * m01 + xc[i10] * m10 + xc[i11] * m11;
        }
    }
    int outbase = ((b * CC + cg * 16) * HH + h) * WW + w;
#pragma unroll
    for (int c = 0; c < 16; ++c) g_avg[outbase + c * HW] = acc[c];
}

// ============================================================
// Kernel 3b (R8 exact): weights -> fp16 per tap. grid 50 (tap 49 = 0).
// ============================================================
__global__ __launch_bounds__(256) void k_prepw(const float* __restrict__ fw) {
    int t = blockIdx.x;
    for (int e = threadIdx.x; e < CC * CC; e += 256) {
        int co = e >> 6, ci = e & 63;
        float v = (t < 49) ? fw[(size_t)(co * CC + ci) * 49 + t] : 0.0f;
        g_wt[(size_t)t * (CC * CC) + e] = __half_as_ushort(__float2half_rn(v));
    }
}

// ============================================================
// Kernel 4 (R8 exact): 7x7 conv via mma.sync implicit GEMM, taps-outer.
// Single-pass fp16, 25 two-tap stages, 2 blocks/SM. grid (11, 25, 1)/batch.
// ============================================================
#define ASTRIDE 144
#define AS_SZ 54720                       // 380 * 144
#define BS_OFF(buf) (AS_SZ + (buf) * 18432)
#define SMEM_TC 91584

__global__ void __launch_bounds__(256, 2) k_conv_mma(float* __restrict__ out,
                                                     const float* __restrict__ bias, int b) {
    extern __shared__ unsigned char smem[];
    uint32_t sb = smem_u32(smem);
    int tid = threadIdx.x;
    int lane = tid & 31, wrp = tid >> 5;
    int mw = wrp & 3, nw = wrp >> 2;
    int h0 = blockIdx.y * 4, w0 = blockIdx.x * 32;

    float acc[2][4][4];
#pragma unroll
    for (int mt = 0; mt < 2; ++mt)
#pragma unroll
        for (int nt = 0; nt < 4; ++nt)
#pragma unroll
            for (int r = 0; r < 4; ++r) acc[mt][nt][r] = 0.0f;

    int tl = lane >> 3;
    int a_roff = (lane & 7) + (tl & 1) * 8;
    int a_coff = (tl >> 1) * 8;
    int b_roff = lane & 7;
    int b_coff = ((lane >> 3) & 1) * 8;

    uint32_t aBase[2];
#pragma unroll
    for (int mt = 0; mt < 2; ++mt) {
        int px = mw * 32 + mt * 16 + a_roff;
        int pr = px >> 5, pc = px & 31;
        aBase[mt] = sb + (uint32_t)(pr * 38 + pc) * ASTRIDE + (uint32_t)a_coff * 2;
    }
    uint32_t bBase = (uint32_t)(nw * 32 + b_roff) * ASTRIDE + (uint32_t)b_coff * 2;

    int b_co0 = tid >> 3, b_f4 = tid & 7;

    const float* inb = g_avg + (size_t)b * CC * HW;

    // ---- build A_ext once: 380 ext px x 64 ci, fp16 ----
#pragma unroll 4
    for (int it = 0; it < 96; ++it) {
        int idx = tid + it * 256;                 // 0..24575 = 64 ci * 384 slots
        int ci = idx / 384, p = idx - ci * 384;
        if (p < 380) {
            int er = p / 38, ec = p - er * 38;
            int gh = h0 - 3 + er, gw = w0 - 3 + ec;
            float v = 0.0f;
            if (gh >= 0 && gh < HH && gw >= 0 && gw < WW) v = inb[(size_t)ci * HW + gh * WW + gw];
            *(unsigned short*)(smem + p * ASTRIDE + ci * 2) =
                __half_as_ushort(__float2half_rn(v));
        }
    }
    // ---- stage B taps 0,1 into buffer 0 ----
    {
        const float4* s0 = (const float4*)(g_wt);
        const float4* s1 = (const float4*)(g_wt + (size_t)1 * (CC * CC));
        float4* d0 = (float4*)(smem + BS_OFF(0));
        float4* d1 = (float4*)(smem + BS_OFF(0) + 9216);
        d0[b_co0 * 9 + b_f4] = s0[tid];
        d0[(b_co0 + 32) * 9 + b_f4] = s0[tid + 256];
        d1[b_co0 * 9 + b_f4] = s1[tid];
        d1[(b_co0 + 32) * 9 + b_f4] = s1[tid + 256];
    }
    __syncthreads();

    for (int s = 0; s < 25; ++s) {
        int buf = s & 1;
        bool have_next = (s + 1 < 25);
        float4 v00, v01, v10, v11;
        if (have_next) {
            const float4* s0 = (const float4*)(g_wt + (size_t)(2 * s + 2) * (CC * CC));
            const float4* s1 = (const float4*)(g_wt + (size_t)(2 * s + 3) * (CC * CC));
            v00 = s0[tid]; v01 = s0[tid + 256];
            v10 = s1[tid]; v11 = s1[tid + 256];
        }

#pragma unroll
        for (int ti = 0; ti < 2; ++ti) {
            int t = 2 * s + ti;
            int toff = (t < 49) ? ((t / 7) * 38 + (t % 7)) * ASTRIDE : 0;  // pad tap: w=0
            uint32_t bptr = sb + BS_OFF(buf) + (uint32_t)ti * 9216 + bBase;
#pragma unroll
            for (int j = 0; j < 4; ++j) {
                uint32_t Ah[2][4];
#pragma unroll
                for (int mt = 0; mt < 2; ++mt)
                    LDMATRIX_X4(Ah[mt], aBase[mt] + (uint32_t)toff + (uint32_t)j * 32);
#pragma unroll
                for (int nt = 0; nt < 4; ++nt) {
                    uint32_t Bf[2];
                    LDMATRIX_X2(Bf, bptr + (uint32_t)(nt * 8) * ASTRIDE + (uint32_t)j * 32);
#pragma unroll
                    for (int mt = 0; mt < 2; ++mt)
                        MMA_F16(acc[mt][nt], Ah[mt], Bf);
                }
            }
        }

        if (have_next) {
            int nb = buf ^ 1;
            float4* d0 = (float4*)(smem + BS_OFF(nb));
            float4* d1 = (float4*)(smem + BS_OFF(nb) + 9216);
            d0[b_co0 * 9 + b_f4] = v00;
            d0[(b_co0 + 32) * 9 + b_f4] = v01;
            d1[b_co0 * 9 + b_f4] = v10;
            d1[(b_co0 + 32) * 9 + b_f4] = v11;
        }
        __syncthreads();
    }

    // ---- epilogue ----
    int g = lane >> 2, tig = lane & 3;
    float* o = out + (size_t)b * CC * HW;
#pragma unroll
    for (int mt = 0; mt < 2; ++mt) {
        int r0 = mw * 32 + mt * 16 + g;
        int oh0 = h0 + (r0 >> 5), ow0 = w0 + (r0 & 31);
        int r1 = r0 + 8;
        int oh1 = h0 + (r1 >> 5), ow1 = w0 + (r1 & 31);
#pragma unroll
        for (int nt = 0; nt < 4; ++nt) {
            int co = nw * 32 + nt * 8 + tig * 2;
            float bv0 = __ldg(&bias[co]), bv1 = __ldg(&bias[co + 1]);
            o[(size_t)co * HW + oh0 * WW + ow0] = acc[mt][nt][0] + bv0;
            o[(size_t)(co + 1) * HW + oh0 * WW + ow0] = acc[mt][nt][1] + bv1;
            o[(size_t)co * HW + oh1 * WW + ow1] = acc[mt][nt][2] + bv0;
            o[(size_t)(co + 1) * HW + oh1 * WW + ow1] = acc[mt][nt][3] + bv1;
        }
    }
}

// ============================================================
// Launch: two per-batch chains forked onto a second stream via events.
// ============================================================
extern "C" void kernel_launch(void* const* d_in, const int* in_sizes, int n_in,
                              void* d_out, int out_size) {
    const float* x   = (const float*)d_in[0];  // (10,64,100,352)
    const float* psm = (const float*)d_in[1];  // (10,2,100,352)
    // d_in[2] record_len: unused
    const float* pt  = (const float*)d_in[3];  // (2,5,5,4,4)
    const float* fw  = (const float*)d_in[4];  // (64,64,7,7)
    const float* fb  = (const float*)d_in[5];  // (64,)
    float* out = (float*)d_out;                // (2,64,100,352)

    static bool inited = false;
    static cudaStream_t sB = 0;
    static cudaEvent_t evF0 = 0, evP = 0, evJ1 = 0;
    if (!inited) {
        cudaFuncSetAttribute(k_conv_mma, cudaFuncAttributeMaxDynamicSharedMemorySize, SMEM_TC);
        cudaFuncSetAttribute(k_select, cudaFuncAttributeMaxDynamicSharedMemorySize, SEL_SMEM);
        if (cudaStreamCreateWithFlags(&sB, cudaStreamNonBlocking) != cudaSuccess) sB = 0;
        if (sB) {
            if (cudaEventCreateWithFlags(&evF0, cudaEventDisableTiming) != cudaSuccess ||
                cudaEventCreateWithFlags(&evP, cudaEventDisableTiming) != cudaSuccess ||
                cudaEventCreateWithFlags(&evJ1, cudaEventDisableTiming) != cudaSuccess) {
                sB = 0;
            }
        }
        inited = true;
    }

    const int nconf = (LL * HW + 255) / 256;

    if (sB) {
        cudaEventRecord(evF0, 0);
        cudaStreamWaitEvent(sB, evF0, 0);

        // stream sB: batch 1 chain (+ weight prep, consumed by both convs)
        k_prepw<<<50, 256, 0, sB>>>(fw);
        cudaEventRecord(evP, sB);
        k_conf<<<nconf, 256, 0, sB>>>(psm, LL);
        k_confwarp<<<dim3(HH, LL), WW, 0, sB>>>(pt, LL);
        k_select<<<LL, 1024, SEL_SMEM, sB>>>(LL);
        k_warpacc<<<dim3(HH, 4, 1), WW, 0, sB>>>(x, pt, 1);
        k_conv_mma<<<dim3(WW / 32, HH / 4, 1), 256, SMEM_TC, sB>>>(out, fb, 1);
        cudaEventRecord(evJ1, sB);

        // stream 0: batch 0 chain
        k_conf<<<nconf, 256>>>(psm, 0);
        k_confwarp<<<dim3(HH, LL), WW>>>(pt, 0);
        k_select<<<LL, 1024, SEL_SMEM>>>(0);
        k_warpacc<<<dim3(HH, 4, 1), WW>>>(x, pt, 0);
        cudaStreamWaitEvent(0, evP, 0);
        k_conv_mma<<<dim3(WW / 32, HH / 4, 1), 256, SMEM_TC>>>(out, fb, 0);

        cudaStreamWaitEvent(0, evJ1, 0);
    } else {
        // fallback: single-stream sequence
        k_prepw<<<50, 256>>>(fw);
        k_conf<<<nconf, 256>>>(psm, 0);
        k_conf<<<nconf, 256>>>(psm, LL);
        k_confwarp<<<dim3(HH, LL), WW>>>(pt, 0);
        k_confwarp<<<dim3(HH, LL), WW>>>(pt, LL);
        k_select<<<LL, 1024, SEL_SMEM>>>(0);
        k_select<<<LL, 1024, SEL_SMEM>>>(LL);
        k_warpacc<<<dim3(HH, 4, 1), WW>>>(x, pt, 0);
        k_warpacc<<<dim3(HH, 4, 1), WW>>>(x, pt, 1);
        k_conv_mma<<<dim3(WW / 32, HH / 4, 1), 256, SMEM_TC>>>(out, fb, 0);
        k_conv_mma<<<dim3(WW / 32, HH / 4, 1), 256, SMEM_TC>>>(out, fb, 1);
    }
}

// round 16
// speedup vs baseline: 1.2907x; 1.0474x over previous
#include <cuda_runtime.h>
#include <cuda_fp16.h>
#include <math.h>
#include <stdint.h>

#define NIMG 10
#define BB 2
#define LL 5
#define CC 64
#define HH 100
#define WW 352
#define HW 35200
#define KSEL 8800

// ---- scratch (static device globals; no allocation) ----
__device__ float g_conf[NIMG * HW];    // sigmoid(max psm) map (bit-exact vs XLA)
__device__ float g_confw[NIMG * HW];   // warped confidence (bit-exact vs XLA)
__device__ float g_thr[NIMG];          // per-sample K-th largest conf value
__device__ float g_avg[BB * CC * HW];  // (1/L) * sum_l sparse_l, per batch
// conv weights per tap, fp16: [t][co][ci]
__device__ unsigned short g_wt[50 * CC * CC];

// scale constants, computed in double then rounded to f32 (matches Python)
#define S01 ((float)(100.0 / 352.0))
#define S02 ((float)(2.0 / (2.0 * 0.4 * 352.0)))
#define S10 ((float)(352.0 / 100.0))
#define S12 ((float)(2.0 / (2.0 * 0.4 * 100.0)))
#define CXW ((float)(2.0 / 352.0))
#define CYH ((float)(2.0 / 100.0))

// ============================================================
// mma.sync / ldmatrix helpers (baseline PTX, sm_80+; OK on sm_103 plain)
// ============================================================
static __device__ __forceinline__ uint32_t smem_u32(const void* p) {
    uint32_t a;
    asm("{ .reg .u64 t; cvta.to.shared.u64 t, %1; cvt.u32.u64 %0, t; }" : "=r"(a) : "l"(p));
    return a;
}

#define LDMATRIX_X4(r, addr) \
    asm volatile("ldmatrix.sync.aligned.m8n8.x4.shared.b16 {%0,%1,%2,%3}, [%4];" \
        : "=r"((r)[0]), "=r"((r)[1]), "=r"((r)[2]), "=r"((r)[3]) : "r"(addr))

#define MMA_F16(d, a, bfr) \
    asm volatile("mma.sync.aligned.m16n8k16.row.col.f32.f16.f16.f32 " \
        "{%0,%1,%2,%3}, {%4,%5,%6,%7}, {%8,%9}, {%0,%1,%2,%3};" \
        : "+f"((d)[0]), "+f"((d)[1]), "+f"((d)[2]), "+f"((d)[3]) \
        : "r"((a)[0]), "r"((a)[1]), "r"((a)[2]), "r"((a)[3]), "r"((bfr)[0]), "r"((bfr)[1]))

// ---- XLA f32 tanh (Eigen-style rational approx, uncontracted mul/add) ----
__device__ __forceinline__ float xla_tanh(float x) {
    float cx = fminf(fmaxf(x, -7.90531110763549805f), 7.90531110763549805f);
    float x2 = __fmul_rn(cx, cx);
    float p = -2.76076847742355e-16f;
    p = __fadd_rn(__fmul_rn(p, x2), 2.00018790482477e-13f);
    p = __fadd_rn(__fmul_rn(p, x2), -8.60467152213735e-11f);
    p = __fadd_rn(__fmul_rn(p, x2), 5.12229709037114e-08f);
    p = __fadd_rn(__fmul_rn(p, x2), 1.48572235717979e-05f);
    p = __fadd_rn(__fmul_rn(p, x2), 6.37261928875436e-04f);
    p = __fadd_rn(__fmul_rn(p, x2), 4.89352455891786e-03f);
    float num = __fmul_rn(cx, p);
    float q = 1.19825839466702e-06f;
    q = __fadd_rn(__fmul_rn(q, x2), 1.18534705686654e-04f);
    q = __fadd_rn(__fmul_rn(q, x2), 2.26843463243900e-03f);
    q = __fadd_rn(__fmul_rn(q, x2), 4.89352518554385e-03f);
    float r = __fdiv_rn(num, q);
    return (fabsf(x) < 0.0004f) ? x : r;
}
__device__ __forceinline__ float xla_sigmoid(float x) {
    return __fadd_rn(0.5f, __fmul_rn(0.5f, xla_tanh(__fmul_rn(0.5f, x))));
}

__device__ __forceinline__ void get_theta(const float* __restrict__ pt, int b, int l, float th[6]) {
    const float* p = pt + b * (LL * LL * 16) + l * 16;
    th[0] = p[0];
    th[1] = p[1] * S01;
    th[2] = p[3] * S02;
    th[3] = p[4] * S10;
    th[4] = p[5];
    th[5] = p[7] * S12;
}

// ============================================================
// Kernel 0: conf map = sigmoid(max(psm over 2 ch)), elementwise, strict XLA.
// ============================================================
__global__ __launch_bounds__(256) void k_conf(const float* __restrict__ psm, int base) {
    int i = blockIdx.x * 256 + threadIdx.x;
    if (i < LL * HW) {
        int n = base + i / HW, hw = i - (i / HW) * HW;
        const float* bp = psm + (size_t)n * 2 * HW;
        float m = fmaxf(bp[hw], bp[HW + hw]);
        g_conf[(size_t)n * HW + hw] = xla_sigmoid(m);
    }
}

// ============================================================
// Kernel 1: warp conf map (gather-only; strict fp32 sequence; bit-exact).
// grid (H, LL) per batch.
// ============================================================
__global__ __launch_bounds__(WW) void k_confwarp(const float* __restrict__ pt, int base) {
    int h = blockIdx.x, n = base + blockIdx.y, w = threadIdx.x;
    int b = n / LL, l = n % LL;
    const float* p = pt + b * (LL * LL * 16) + l * 16;
    float th0 = p[0];
    float th1 = __fmul_rn(p[1], S01);
    float th2 = __fmul_rn(p[3], S02);
    float th3 = __fmul_rn(p[4], S10);
    float th4 = p[5];
    float th5 = __fmul_rn(p[7], S12);

    float gx = __fsub_rn(__fmul_rn(__fadd_rn((float)w, 0.5f), CXW), 1.0f);
    float gy = __fsub_rn(__fmul_rn(__fadd_rn((float)h, 0.5f), CYH), 1.0f);
    float src_x = __fadd_rn(__fadd_rn(__fmul_rn(th0, gx), __fmul_rn(th1, gy)), th2);
    float src_y = __fadd_rn(__fadd_rn(__fmul_rn(th3, gx), __fmul_rn(th4, gy)), th5);
    float px = __fsub_rn(__fmul_rn(__fadd_rn(src_x, 1.0f), 176.0f), 0.5f);
    float py = __fsub_rn(__fmul_rn(__fadd_rn(src_y, 1.0f), 50.0f), 0.5f);
    float x0 = floorf(px), y0 = floorf(py);
    float wx1 = __fsub_rn(px, x0), wx0 = __fsub_rn(1.0f, wx1);
    float wy1 = __fsub_rn(py, y0), wy0 = __fsub_rn(1.0f, wy1);

    const float* cmap = g_conf + (size_t)n * HW;
    float acc = 0.0f;
#pragma unroll
    for (int dy = 0; dy < 2; ++dy) {
#pragma unroll
        for (int dx = 0; dx < 2; ++dx) {
            float yy = dy ? __fadd_rn(y0, 1.0f) : y0;
            float xx = dx ? __fadd_rn(x0, 1.0f) : x0;
            if (yy >= 0.0f && yy <= (float)(HH - 1) && xx >= 0.0f && xx <= (float)(WW - 1)) {
                int yi = (int)yy, xi = (int)xx;
                float s = cmap[yi * WW + xi];
                float wgt = __fmul_rn(dy ? wy1 : wy0, dx ? wx1 : wx0);
                acc = __fadd_rn(acc, __fmul_rn(s, wgt));
            }
        }
    }
    g_confw[n * HW + h * WW + w] = acc;
}

// ============================================================
// Kernel 2 (R14 exact): 4x8-bit radix select, keys staged to shared.
// ============================================================
#define SEL_SMEM (HW * 4)

__device__ __forceinline__ void sel_pick(unsigned int* hist, unsigned int* sfx,
                                         unsigned int* s_prefix, unsigned int* s_krem,
                                         unsigned int prefix, int shift, int tid) {
    if (tid < 256) sfx[tid] = hist[tid];
    __syncthreads();
#pragma unroll
    for (int off = 1; off < 256; off <<= 1) {
        unsigned int add = (tid < 256 && tid + off < 256) ? sfx[tid + off] : 0u;
        __syncthreads();
        if (tid < 256) sfx[tid] += add;
        __syncthreads();
    }
    unsigned int krem = *s_krem;
    if (tid < 256) {
        unsigned int S = sfx[tid];
        unsigned int Sn = (tid == 255) ? 0u : sfx[tid + 1];
        if (S >= krem && Sn < krem) {
            *s_prefix = prefix | ((unsigned int)tid << shift);
            *s_krem = krem - Sn;
        }
    }
    __syncthreads();
}

__global__ __launch_bounds__(1024) void k_select(int base) {
    extern __shared__ unsigned int keys[];
    __shared__ unsigned int hist[256];
    __shared__ unsigned int sfx[256];
    __shared__ unsigned int s_prefix, s_krem;
    int n = base + blockIdx.x;
    const unsigned int* v = (const unsigned int*)(g_confw + (size_t)n * HW);
    int tid = threadIdx.x;
    if (tid == 0) { s_prefix = 0u; s_krem = KSEL; }
    if (tid < 256) hist[tid] = 0u;
    __syncthreads();

#pragma unroll
    for (int bt = 0; bt < 4; ++bt) {
        int i0 = bt * 8192 + tid;
        unsigned int kk[8];
#pragma unroll
        for (int j = 0; j < 8; ++j) kk[j] = v[i0 + j * 1024];
#pragma unroll
        for (int j = 0; j < 8; ++j) {
            keys[i0 + j * 1024] = kk[j];
            atomicAdd(&hist[(kk[j] >> 24) & 255u], 1u);
        }
    }
    {
        unsigned int k0 = v[32768 + tid];
        unsigned int k1 = v[33792 + tid];
        unsigned int k2 = (tid < 384) ? v[34816 + tid] : 0u;
        keys[32768 + tid] = k0; atomicAdd(&hist[(k0 >> 24) & 255u], 1u);
        keys[33792 + tid] = k1; atomicAdd(&hist[(k1 >> 24) & 255u], 1u);
        if (tid < 384) { keys[34816 + tid] = k2; atomicAdd(&hist[(k2 >> 24) & 255u], 1u); }
    }
    __syncthreads();
    sel_pick(hist, sfx, &s_prefix, &s_krem, 0u, 24, tid);

    for (int pass = 1; pass < 4; ++pass) {
        int shift = 24 - pass * 8;
        unsigned int pmask = 0xFFFFFFFFu << (shift + 8);
        if (tid < 256) hist[tid] = 0u;
        __syncthreads();
        unsigned int prefix = s_prefix;
#pragma unroll 2
        for (int it = 0; it < 8; ++it) {
            int i = it * 4096 + tid;
            unsigned int k0 = keys[i];
            unsigned int k1 = keys[i + 1024];
            unsigned int k2 = keys[i + 2048];
            unsigned int k3 = keys[i + 3072];
            if ((k0 & pmask) == prefix) atomicAdd(&hist[(k0 >> shift) & 255u], 1u);
            if ((k1 & pmask) == prefix) atomicAdd(&hist[(k1 >> shift) & 255u], 1u);
            if ((k2 & pmask) == prefix) atomicAdd(&hist[(k2 >> shift) & 255u], 1u);
            if ((k3 & pmask) == prefix) atomicAdd(&hist[(k3 >> shift) & 255u], 1u);
        }
        {
            unsigned int k0 = keys[32768 + tid];
            unsigned int k1 = keys[33792 + tid];
            unsigned int k2 = (tid < 384) ? keys[34816 + tid] : 0u;
            if ((k0 & pmask) == prefix) atomicAdd(&hist[(k0 >> shift) & 255u], 1u);
            if ((k1 & pmask) == prefix) atomicAdd(&hist[(k1 >> shift) & 255u], 1u);
            if (tid < 384 && (k2 & pmask) == prefix) atomicAdd(&hist[(k2 >> shift) & 255u], 1u);
        }
        __syncthreads();
        sel_pick(hist, sfx, &s_prefix, &s_krem, s_prefix, shift, tid);
    }
    if (tid == 0) g_thr[n] = __uint_as_float(s_prefix);
}

// ============================================================
// Kernel 3 (R14 exact): warp x + mask + (1/L)-accumulate, prefetched gates.
// ============================================================
__global__ __launch_bounds__(WW) void k_warpacc(const float* __restrict__ x,
                                                const float* __restrict__ pt, int b) {
    int h = blockIdx.x, cg = blockIdx.y, w = threadIdx.x;
    float acc[16];
#pragma unroll
    for (int i = 0; i < 16; ++i) acc[i] = 0.0f;
    float gx = (w + 0.5f) * (2.0f / WW) - 1.0f;
    float gy = (h + 0.5f) * (2.0f / HH) - 1.0f;

    float cw[LL], tr[LL];
    int hw = h * WW + w;
#pragma unroll
    for (int l = 0; l < LL; ++l) {
        int n = b * LL + l;
        cw[l] = g_confw[(size_t)n * HW + hw];
        tr[l] = g_thr[n];
    }

    for (int l = 0; l < LL; ++l) {
        if (l != 0 && cw[l] < tr[l]) continue;
        float th[6];
        get_theta(pt, b, l, th);
        int n = b * LL + l;
        float px = (th[0] * gx + th[1] * gy + th[2] + 1.0f) * (WW * 0.5f) - 0.5f;
        float py = (th[3] * gx + th[4] * gy + th[5] + 1.0f) * (HH * 0.5f) - 0.5f;
        float x0 = floorf(px), y0 = floorf(py);
        float wx1 = px - x0, wx0 = 1.0f - wx1;
        float wy1 = py - y0, wy0 = 1.0f - wy1;
        bool vx0 = (x0 >= 0.0f) && (x0 <= (float)(WW - 1));
        bool vx1 = (x0 + 1.0f >= 0.0f) && (x0 + 1.0f <= (float)(WW - 1));
        bool vy0 = (y0 >= 0.0f) && (y0 <= (float)(HH - 1));
        bool vy1 = (y0 + 1.0f >= 0.0f) && (y0 + 1.0f <= (float)(HH - 1));
        int x0i = (int)fminf(fmaxf(x0, 0.0f), (float)(WW - 1));
        int x1i = (int)fminf(fmaxf(x0 + 1.0f, 0.0f), (float)(WW - 1));
        int y0i = (int)fminf(fmaxf(y0, 0.0f), (float)(HH - 1));
        int y1i = (int)fminf(fmaxf(y0 + 1.0f, 0.0f), (float)(HH - 1));
        float m00 = (vy0 && vx0) ? wy0 * wx0 * 0.2f : 0.0f;
        float m01 = (vy0 && vx1) ? wy0 * wx1 * 0.2f : 0.0f;
        float m10 = (vy1 && vx0) ? wy1 * wx0 * 0.2f : 0.0f;
        float m11 = (vy1 && vx1) ? wy1 * wx1 * 0.2f : 0.0f;
        int i00 = y0i * WW + x0i, i01 = y0i * WW + x1i;
        int i10 = y1i * WW + x0i, i11 = y1i * WW + x1i;
        const float* xb = x + (size_t)(n * CC + cg * 16) * HW;
#pragma unroll
        for (int c = 0; c < 16; ++c) {
            const float* xc = xb + c * HW;
            acc[c] += xc[i00] * m00 + xc[i01] * m01 + xc[i10] * m10 + xc[i11] * m11;
        }
    }
    int outbase = ((b * CC + cg * 16) * HH + h) * WW + w;
#pragma unroll
    for (int c = 0; c < 16; ++c) g_avg[outbase + c * HW] = acc[c];
}

// ============================================================
// Kernel 3b: weights -> fp16 per tap. grid 49.
// ============================================================
__global__ __launch_bounds__(256) void k_prepw(const float* __restrict__ fw) {
    int t = blockIdx.x;
    for (int e = threadIdx.x; e < CC * CC; e += 256) {
        int co = e >> 6, ci = e & 63;
        float v = fw[(size_t)(co * CC + ci) * 49 + t];
        g_wt[(size_t)t * (CC * CC) + e] = __half_as_ushort(__float2half_rn(v));
    }
}

// ============================================================
// Kernel 4: 7x7 conv via mma.sync implicit GEMM, taps-outer / K=ci.
// NEW: B fragments via ldmatrix.x4 (2 nt per LDSM; 16 vs 24 LDSM/tap) and
// 3 blocks/SM (single-tap double buffer, smem 73.2KB, 6 warps/SMSP).
// ============================================================
#define ASTRIDE 144
#define AS_SZ 54720                       // 380 * 144
#define BS_OFF(buf) (AS_SZ + (buf) * 9216)
#define SMEM_TC 73152

__global__ void __launch_bounds__(256, 3) k_conv_mma(float* __restrict__ out,
                                                     const float* __restrict__ bias, int b) {
    extern __shared__ unsigned char smem[];
    uint32_t sb = smem_u32(smem);
    int tid = threadIdx.x;
    int lane = tid & 31, wrp = tid >> 5;
    int mw = wrp & 3, nw = wrp >> 2;
    int h0 = blockIdx.y * 4, w0 = blockIdx.x * 32;

    float acc[2][4][4];
#pragma unroll
    for (int mt = 0; mt < 2; ++mt)
#pragma unroll
        for (int nt = 0; nt < 4; ++nt)
#pragma unroll
            for (int r = 0; r < 4; ++r) acc[mt][nt][r] = 0.0f;

    int tl = lane >> 3;
    int a_roff = (lane & 7) + (tl & 1) * 8;
    int a_coff = (tl >> 1) * 8;
    // B x4 lane mapping: q = lane>>3 -> {row+0,k0},{row+0,k8},{row+8,k0},{row+8,k8}
    int b4_roff = (lane & 7) + ((lane >> 4) & 1) * 8;
    int b4_coff = ((lane >> 3) & 1) * 8;

    uint32_t aBase[2];
#pragma unroll
    for (int mt = 0; mt < 2; ++mt) {
        int px = mw * 32 + mt * 16 + a_roff;
        int pr = px >> 5, pc = px & 31;
        aBase[mt] = sb + (uint32_t)(pr * 38 + pc) * ASTRIDE + (uint32_t)a_coff * 2;
    }
    // per nt-pair p: row = nw*32 + p*16 + b4_roff
    uint32_t bBase4 = (uint32_t)(nw * 32 + b4_roff) * ASTRIDE + (uint32_t)b4_coff * 2;

    int b_co0 = tid >> 3, b_f4 = tid & 7;

    const float* inb = g_avg + (size_t)b * CC * HW;

    // ---- build A_ext once: 380 ext px x 64 ci, fp16 ----
#pragma unroll 4
    for (int it = 0; it < 96; ++it) {
        int idx = tid + it * 256;
        int ci = idx / 384, p = idx - ci * 384;
        if (p < 380) {
            int er = p / 38, ec = p - er * 38;
            int gh = h0 - 3 + er, gw = w0 - 3 + ec;
            float v = 0.0f;
            if (gh >= 0 && gh < HH && gw >= 0 && gw < WW) v = inb[(size_t)ci * HW + gh * WW + gw];
            *(unsigned short*)(smem + p * ASTRIDE + ci * 2) =
                __half_as_ushort(__float2half_rn(v));
        }
    }
    // ---- stage B tap 0 into buffer 0 ----
    {
        const float4* s0 = (const float4*)(g_wt);
        float4* d0 = (float4*)(smem + BS_OFF(0));
        d0[b_co0 * 9 + b_f4] = s0[tid];
        d0[(b_co0 + 32) * 9 + b_f4] = s0[tid + 256];
    }
    __syncthreads();

    int toff = 0;
    int kx = 0;
    for (int t = 0; t < 49; ++t) {
        int buf = t & 1;
        bool have_next = (t + 1 < 49);
        float4 v0, v1;
        if (have_next) {
            const float4* s0 = (const float4*)(g_wt + (size_t)(t + 1) * (CC * CC));
            v0 = s0[tid]; v1 = s0[tid + 256];
        }

        uint32_t bptr = sb + BS_OFF(buf) + bBase4;
#pragma unroll
        for (int j = 0; j < 4; ++j) {
            uint32_t Ah[2][4];
#pragma unroll
            for (int mt = 0; mt < 2; ++mt)
                LDMATRIX_X4(Ah[mt], aBase[mt] + (uint32_t)toff + (uint32_t)j * 32);
#pragma unroll
            for (int p = 0; p < 2; ++p) {   // nt pairs (0,1) and (2,3)
                uint32_t Bf[4];
                LDMATRIX_X4(Bf, bptr + (uint32_t)(p * 16) * ASTRIDE + (uint32_t)j * 32);
#pragma unroll
                for (int mt = 0; mt < 2; ++mt) {
                    MMA_F16(acc[mt][p * 2], Ah[mt], Bf);       // {Bf[0],Bf[1]}
                    MMA_F16(acc[mt][p * 2 + 1], Ah[mt], Bf + 2); // {Bf[2],Bf[3]}
                }
            }
        }

        if (have_next) {
            int nb = buf ^ 1;
            float4* d0 = (float4*)(smem + BS_OFF(nb));
            d0[b_co0 * 9 + b_f4] = v0;
            d0[(b_co0 + 32) * 9 + b_f4] = v1;
        }
        __syncthreads();

        ++kx;
        if (kx == 7) { kx = 0; toff += 32 * ASTRIDE; }
        else toff += ASTRIDE;
    }

    // ---- epilogue ----
    int g = lane >> 2, tig = lane & 3;
    float* o = out + (size_t)b * CC * HW;
#pragma unroll
    for (int mt = 0; mt < 2; ++mt) {
        int r0 = mw * 32 + mt * 16 + g;
        int oh0 = h0 + (r0 >> 5), ow0 = w0 + (r0 & 31);
        int r1 = r0 + 8;
        int oh1 = h0 + (r1 >> 5), ow1 = w0 + (r1 & 31);
#pragma unroll
        for (int nt = 0; nt < 4; ++nt) {
            int co = nw * 32 + nt * 8 + tig * 2;
            float bv0 = __ldg(&bias[co]), bv1 = __ldg(&bias[co + 1]);
            o[(size_t)co * HW + oh0 * WW + ow0] = acc[mt][nt][0] + bv0;
            o[(size_t)(co + 1) * HW + oh0 * WW + ow0] = acc[mt][nt][1] + bv1;
            o[(size_t)co * HW + oh1 * WW + ow1] = acc[mt][nt][2] + bv0;
            o[(size_t)(co + 1) * HW + oh1 * WW + ow1] = acc[mt][nt][3] + bv1;
        }
    }
}

// ============================================================
// Launch: two per-batch chains forked onto a second stream via events.
// ============================================================
extern "C" void kernel_launch(void* const* d_in, const int* in_sizes, int n_in,
                              void* d_out, int out_size) {
    const float* x   = (const float*)d_in[0];  // (10,64,100,352)
    const float* psm = (const float*)d_in[1];  // (10,2,100,352)
    // d_in[2] record_len: unused
    const float* pt  = (const float*)d_in[3];  // (2,5,5,4,4)
    const float* fw  = (const float*)d_in[4];  // (64,64,7,7)
    const float* fb  = (const float*)d_in[5];  // (64,)
    float* out = (float*)d_out;                // (2,64,100,352)

    static bool inited = false;
    static cudaStream_t sB = 0;
    static cudaEvent_t evF0 = 0, evP = 0, evJ1 = 0;
    if (!inited) {
        cudaFuncSetAttribute(k_conv_mma, cudaFuncAttributeMaxDynamicSharedMemorySize, SMEM_TC);
        cudaFuncSetAttribute(k_select, cudaFuncAttributeMaxDynamicSharedMemorySize, SEL_SMEM);
        if (cudaStreamCreateWithFlags(&sB, cudaStreamNonBlocking) != cudaSuccess) sB = 0;
        if (sB) {
            if (cudaEventCreateWithFlags(&evF0, cudaEventDisableTiming) != cudaSuccess ||
                cudaEventCreateWithFlags(&evP, cudaEventDisableTiming) != cudaSuccess ||
                cudaEventCreateWithFlags(&evJ1, cudaEventDisableTiming) != cudaSuccess) {
                sB = 0;
            }
        }
        inited = true;
    }

    const int nconf = (LL * HW + 255) / 256;

    if (sB) {
        cudaEventRecord(evF0, 0);
        cudaStreamWaitEvent(sB, evF0, 0);

        // stream sB: batch 1 chain (+ weight prep, consumed by both convs)
        k_prepw<<<49, 256, 0, sB>>>(fw);
        cudaEventRecord(evP, sB);
        k_conf<<<nconf, 256, 0, sB>>>(psm, LL);
        k_confwarp<<<dim3(HH, LL), WW, 0, sB>>>(pt, LL);
        k_select<<<LL, 1024, SEL_SMEM, sB>>>(LL);
        k_warpacc<<<dim3(HH, 4, 1), WW, 0, sB>>>(x, pt, 1);
        k_conv_mma<<<dim3(WW / 32, HH / 4, 1), 256, SMEM_TC, sB>>>(out, fb, 1);
        cudaEventRecord(evJ1, sB);

        // stream 0: batch 0 chain
        k_conf<<<nconf, 256>>>(psm, 0);
        k_confwarp<<<dim3(HH, LL), WW>>>(pt, 0);
        k_select<<<LL, 1024, SEL_SMEM>>>(0);
        k_warpacc<<<dim3(HH, 4, 1), WW>>>(x, pt, 0);
        cudaStreamWaitEvent(0, evP, 0);
        k_conv_mma<<<dim3(WW / 32, HH / 4, 1), 256, SMEM_TC>>>(out, fb, 0);

        cudaStreamWaitEvent(0, evJ1, 0);
    } else {
        // fallback: single-stream sequence
        k_prepw<<<49, 256>>>(fw);
        k_conf<<<nconf, 256>>>(psm, 0);
        k_conf<<<nconf, 256>>>(psm, LL);
        k_confwarp<<<dim3(HH, LL), WW>>>(pt, 0);
        k_confwarp<<<dim3(HH, LL), WW>>>(pt, LL);
        k_select<<<LL, 1024, SEL_SMEM>>>(0);
        k_select<<<LL, 1024, SEL_SMEM>>>(LL);
        k_warpacc<<<dim3(HH, 4, 1), WW>>>(x, pt, 0);
        k_warpacc<<<dim3(HH, 4, 1), WW>>>(x, pt, 1);
        k_conv_mma<<<dim3(WW / 32, HH / 4, 1), 256, SMEM_TC>>>(out, fb, 0);
        k_conv_mma<<<dim3(WW / 32, HH / 4, 1), 256, SMEM_TC>>>(out, fb, 1);
    }
}

// round 17
// speedup vs baseline: 1.3990x; 1.0839x over previous
#include <cuda_runtime.h>
#include <cuda_fp16.h>
#include <math.h>
#include <stdint.h>

#define NIMG 10
#define BB 2
#define LL 5
#define CC 64
#define HH 100
#define WW 352
#define HW 35200
#define KSEL 8800

// ---- scratch (static device globals; no allocation) ----
__device__ float g_conf[NIMG * HW];    // sigmoid(max psm) map (bit-exact vs XLA)
__device__ float g_confw[NIMG * HW];   // warped confidence (bit-exact vs XLA)
__device__ float g_thr[NIMG];          // per-sample K-th largest conf value
__device__ float g_avg[BB * CC * HW];  // (1/L) * sum_l sparse_l, per batch
// conv weights per tap, fp16: [t][co][ci]
__device__ unsigned short g_wt[50 * CC * CC];

// scale constants, computed in double then rounded to f32 (matches Python)
#define S01 ((float)(100.0 / 352.0))
#define S02 ((float)(2.0 / (2.0 * 0.4 * 352.0)))
#define S10 ((float)(352.0 / 100.0))
#define S12 ((float)(2.0 / (2.0 * 0.4 * 100.0)))
#define CXW ((float)(2.0 / 352.0))
#define CYH ((float)(2.0 / 100.0))

// ============================================================
// mma.sync / ldmatrix helpers (baseline PTX, sm_80+; OK on sm_103 plain)
// ============================================================
static __device__ __forceinline__ uint32_t smem_u32(const void* p) {
    uint32_t a;
    asm("{ .reg .u64 t; cvta.to.shared.u64 t, %1; cvt.u32.u64 %0, t; }" : "=r"(a) : "l"(p));
    return a;
}

#define LDMATRIX_X4(r, addr) \
    asm volatile("ldmatrix.sync.aligned.m8n8.x4.shared.b16 {%0,%1,%2,%3}, [%4];" \
        : "=r"((r)[0]), "=r"((r)[1]), "=r"((r)[2]), "=r"((r)[3]) : "r"(addr))

#define MMA_F16(d, a, bfr) \
    asm volatile("mma.sync.aligned.m16n8k16.row.col.f32.f16.f16.f32 " \
        "{%0,%1,%2,%3}, {%4,%5,%6,%7}, {%8,%9}, {%0,%1,%2,%3};" \
        : "+f"((d)[0]), "+f"((d)[1]), "+f"((d)[2]), "+f"((d)[3]) \
        : "r"((a)[0]), "r"((a)[1]), "r"((a)[2]), "r"((a)[3]), "r"((bfr)[0]), "r"((bfr)[1]))

// ---- XLA f32 tanh (Eigen-style rational approx, uncontracted mul/add) ----
__device__ __forceinline__ float xla_tanh(float x) {
    float cx = fminf(fmaxf(x, -7.90531110763549805f), 7.90531110763549805f);
    float x2 = __fmul_rn(cx, cx);
    float p = -2.76076847742355e-16f;
    p = __fadd_rn(__fmul_rn(p, x2), 2.00018790482477e-13f);
    p = __fadd_rn(__fmul_rn(p, x2), -8.60467152213735e-11f);
    p = __fadd_rn(__fmul_rn(p, x2), 5.12229709037114e-08f);
    p = __fadd_rn(__fmul_rn(p, x2), 1.48572235717979e-05f);
    p = __fadd_rn(__fmul_rn(p, x2), 6.37261928875436e-04f);
    p = __fadd_rn(__fmul_rn(p, x2), 4.89352455891786e-03f);
    float num = __fmul_rn(cx, p);
    float q = 1.19825839466702e-06f;
    q = __fadd_rn(__fmul_rn(q, x2), 1.18534705686654e-04f);
    q = __fadd_rn(__fmul_rn(q, x2), 2.26843463243900e-03f);
    q = __fadd_rn(__fmul_rn(q, x2), 4.89352518554385e-03f);
    float r = __fdiv_rn(num, q);
    return (fabsf(x) < 0.0004f) ? x : r;
}
__device__ __forceinline__ float xla_sigmoid(float x) {
    return __fadd_rn(0.5f, __fmul_rn(0.5f, xla_tanh(__fmul_rn(0.5f, x))));
}

__device__ __forceinline__ void get_theta(const float* __restrict__ pt, int b, int l, float th[6]) {
    const float* p = pt + b * (LL * LL * 16) + l * 16;
    th[0] = p[0];
    th[1] = p[1] * S01;
    th[2] = p[3] * S02;
    th[3] = p[4] * S10;
    th[4] = p[5];
    th[5] = p[7] * S12;
}

// ============================================================
// Kernel 0: conf map = sigmoid(max(psm over 2 ch)), elementwise, strict XLA.
// ============================================================
__global__ __launch_bounds__(256) void k_conf(const float* __restrict__ psm, int base) {
    int i = blockIdx.x * 256 + threadIdx.x;
    if (i < LL * HW) {
        int n = base + i / HW, hw = i - (i / HW) * HW;
        const float* bp = psm + (size_t)n * 2 * HW;
        float m = fmaxf(bp[hw], bp[HW + hw]);
        g_conf[(size_t)n * HW + hw] = xla_sigmoid(m);
    }
}

// ============================================================
// Kernel 1: warp conf map (gather-only; strict fp32 sequence; bit-exact).
// grid (H, LL) per batch.
// ============================================================
__global__ __launch_bounds__(WW) void k_confwarp(const float* __restrict__ pt, int base) {
    int h = blockIdx.x, n = base + blockIdx.y, w = threadIdx.x;
    int b = n / LL, l = n % LL;
    const float* p = pt + b * (LL * LL * 16) + l * 16;
    float th0 = p[0];
    float th1 = __fmul_rn(p[1], S01);
    float th2 = __fmul_rn(p[3], S02);
    float th3 = __fmul_rn(p[4], S10);
    float th4 = p[5];
    float th5 = __fmul_rn(p[7], S12);

    float gx = __fsub_rn(__fmul_rn(__fadd_rn((float)w, 0.5f), CXW), 1.0f);
    float gy = __fsub_rn(__fmul_rn(__fadd_rn((float)h, 0.5f), CYH), 1.0f);
    float src_x = __fadd_rn(__fadd_rn(__fmul_rn(th0, gx), __fmul_rn(th1, gy)), th2);
    float src_y = __fadd_rn(__fadd_rn(__fmul_rn(th3, gx), __fmul_rn(th4, gy)), th5);
    float px = __fsub_rn(__fmul_rn(__fadd_rn(src_x, 1.0f), 176.0f), 0.5f);
    float py = __fsub_rn(__fmul_rn(__fadd_rn(src_y, 1.0f), 50.0f), 0.5f);
    float x0 = floorf(px), y0 = floorf(py);
    float wx1 = __fsub_rn(px, x0), wx0 = __fsub_rn(1.0f, wx1);
    float wy1 = __fsub_rn(py, y0), wy0 = __fsub_rn(1.0f, wy1);

    const float* cmap = g_conf + (size_t)n * HW;
    float acc = 0.0f;
#pragma unroll
    for (int dy = 0; dy < 2; ++dy) {
#pragma unroll
        for (int dx = 0; dx < 2; ++dx) {
            float yy = dy ? __fadd_rn(y0, 1.0f) : y0;
            float xx = dx ? __fadd_rn(x0, 1.0f) : x0;
            if (yy >= 0.0f && yy <= (float)(HH - 1) && xx >= 0.0f && xx <= (float)(WW - 1)) {
                int yi = (int)yy, xi = (int)xx;
                float s = cmap[yi * WW + xi];
                float wgt = __fmul_rn(dy ? wy1 : wy0, dx ? wx1 : wx0);
                acc = __fadd_rn(acc, __fmul_rn(s, wgt));
            }
        }
    }
    g_confw[n * HW + h * WW + w] = acc;
}

// ============================================================
// Kernel 2 (R14 exact): 4x8-bit radix select, keys staged to shared.
// ============================================================
#define SEL_SMEM (HW * 4)

__device__ __forceinline__ void sel_pick(unsigned int* hist, unsigned int* sfx,
                                         unsigned int* s_prefix, unsigned int* s_krem,
                                         unsigned int prefix, int shift, int tid) {
    if (tid < 256) sfx[tid] = hist[tid];
    __syncthreads();
#pragma unroll
    for (int off = 1; off < 256; off <<= 1) {
        unsigned int add = (tid < 256 && tid + off < 256) ? sfx[tid + off] : 0u;
        __syncthreads();
        if (tid < 256) sfx[tid] += add;
        __syncthreads();
    }
    unsigned int krem = *s_krem;
    if (tid < 256) {
        unsigned int S = sfx[tid];
        unsigned int Sn = (tid == 255) ? 0u : sfx[tid + 1];
        if (S >= krem && Sn < krem) {
            *s_prefix = prefix | ((unsigned int)tid << shift);
            *s_krem = krem - Sn;
        }
    }
    __syncthreads();
}

__global__ __launch_bounds__(1024) void k_select(int base) {
    extern __shared__ unsigned int keys[];
    __shared__ unsigned int hist[256];
    __shared__ unsigned int sfx[256];
    __shared__ unsigned int s_prefix, s_krem;
    int n = base + blockIdx.x;
    const unsigned int* v = (const unsigned int*)(g_confw + (size_t)n * HW);
    int tid = threadIdx.x;
    if (tid == 0) { s_prefix = 0u; s_krem = KSEL; }
    if (tid < 256) hist[tid] = 0u;
    __syncthreads();

#pragma unroll
    for (int bt = 0; bt < 4; ++bt) {
        int i0 = bt * 8192 + tid;
        unsigned int kk[8];
#pragma unroll
        for (int j = 0; j < 8; ++j) kk[j] = v[i0 + j * 1024];
#pragma unroll
        for (int j = 0; j < 8; ++j) {
            keys[i0 + j * 1024] = kk[j];
            atomicAdd(&hist[(kk[j] >> 24) & 255u], 1u);
        }
    }
    {
        unsigned int k0 = v[32768 + tid];
        unsigned int k1 = v[33792 + tid];
        unsigned int k2 = (tid < 384) ? v[34816 + tid] : 0u;
        keys[32768 + tid] = k0; atomicAdd(&hist[(k0 >> 24) & 255u], 1u);
        keys[33792 + tid] = k1; atomicAdd(&hist[(k1 >> 24) & 255u], 1u);
        if (tid < 384) { keys[34816 + tid] = k2; atomicAdd(&hist[(k2 >> 24) & 255u], 1u); }
    }
    __syncthreads();
    sel_pick(hist, sfx, &s_prefix, &s_krem, 0u, 24, tid);

    for (int pass = 1; pass < 4; ++pass) {
        int shift = 24 - pass * 8;
        unsigned int pmask = 0xFFFFFFFFu << (shift + 8);
        if (tid < 256) hist[tid] = 0u;
        __syncthreads();
        unsigned int prefix = s_prefix;
#pragma unroll 2
        for (int it = 0; it < 8; ++it) {
            int i = it * 4096 + tid;
            unsigned int k0 = keys[i];
            unsigned int k1 = keys[i + 1024];
            unsigned int k2 = keys[i + 2048];
            unsigned int k3 = keys[i + 3072];
            if ((k0 & pmask) == prefix) atomicAdd(&hist[(k0 >> shift) & 255u], 1u);
            if ((k1 & pmask) == prefix) atomicAdd(&hist[(k1 >> shift) & 255u], 1u);
            if ((k2 & pmask) == prefix) atomicAdd(&hist[(k2 >> shift) & 255u], 1u);
            if ((k3 & pmask) == prefix) atomicAdd(&hist[(k3 >> shift) & 255u], 1u);
        }
        {
            unsigned int k0 = keys[32768 + tid];
            unsigned int k1 = keys[33792 + tid];
            unsigned int k2 = (tid < 384) ? keys[34816 + tid] : 0u;
            if ((k0 & pmask) == prefix) atomicAdd(&hist[(k0 >> shift) & 255u], 1u);
            if ((k1 & pmask) == prefix) atomicAdd(&hist[(k1 >> shift) & 255u], 1u);
            if (tid < 384 && (k2 & pmask) == prefix) atomicAdd(&hist[(k2 >> shift) & 255u], 1u);
        }
        __syncthreads();
        sel_pick(hist, sfx, &s_prefix, &s_krem, s_prefix, shift, tid);
    }
    if (tid == 0) g_thr[n] = __uint_as_float(s_prefix);
}

// ============================================================
// Kernel 3 (R14 exact): warp x + mask + (1/L)-accumulate, prefetched gates.
// ============================================================
__global__ __launch_bounds__(WW) void k_warpacc(const float* __restrict__ x,
                                                const float* __restrict__ pt, int b) {
    int h = blockIdx.x, cg = blockIdx.y, w = threadIdx.x;
    float acc[16];
#pragma unroll
    for (int i = 0; i < 16; ++i) acc[i] = 0.0f;
    float gx = (w + 0.5f) * (2.0f / WW) - 1.0f;
    float gy = (h + 0.5f) * (2.0f / HH) - 1.0f;

    float cw[LL], tr[LL];
    int hw = h * WW + w;
#pragma unroll
    for (int l = 0; l < LL; ++l) {
        int n = b * LL + l;
        cw[l] = g_confw[(size_t)n * HW + hw];
        tr[l] = g_thr[n];
    }

    for (int l = 0; l < LL; ++l) {
        if (l != 0 && cw[l] < tr[l]) continue;
        float th[6];
        get_theta(pt, b, l, th);
        int n = b * LL + l;
        float px = (th[0] * gx + th[1] * gy + th[2] + 1.0f) * (WW * 0.5f) - 0.5f;
        float py = (th[3] * gx + th[4] * gy + th[5] + 1.0f) * (HH * 0.5f) - 0.5f;
        float x0 = floorf(px), y0 = floorf(py);
        float wx1 = px - x0, wx0 = 1.0f - wx1;
        float wy1 = py - y0, wy0 = 1.0f - wy1;
        bool vx0 = (x0 >= 0.0f) && (x0 <= (float)(WW - 1));
        bool vx1 = (x0 + 1.0f >= 0.0f) && (x0 + 1.0f <= (float)(WW - 1));
        bool vy0 = (y0 >= 0.0f) && (y0 <= (float)(HH - 1));
        bool vy1 = (y0 + 1.0f >= 0.0f) && (y0 + 1.0f <= (float)(HH - 1));
        int x0i = (int)fminf(fmaxf(x0, 0.0f), (float)(WW - 1));
        int x1i = (int)fminf(fmaxf(x0 + 1.0f, 0.0f), (float)(WW - 1));
        int y0i = (int)fminf(fmaxf(y0, 0.0f), (float)(HH - 1));
        int y1i = (int)fminf(fmaxf(y0 + 1.0f, 0.0f), (float)(HH - 1));
        float m00 = (vy0 && vx0) ? wy0 * wx0 * 0.2f : 0.0f;
        float m01 = (vy0 && vx1) ? wy0 * wx1 * 0.2f : 0.0f;
        float m10 = (vy1 && vx0) ? wy1 * wx0 * 0.2f : 0.0f;
        float m11 = (vy1 && vx1) ? wy1 * wx1 * 0.2f : 0.0f;
        int i00 = y0i * WW + x0i, i01 = y0i * WW + x1i;
        int i10 = y1i * WW + x0i, i11 = y1i * WW + x1i;
        const float* xb = x + (size_t)(n * CC + cg * 16) * HW;
#pragma unroll
        for (int c = 0; c < 16; ++c) {
            const float* xc = xb + c * HW;
            acc[c] += xc[i00] * m00 + xc[i01] * m01 + xc[i10] * m10 + xc[i11] * m11;
        }
    }
    int outbase = ((b * CC + cg * 16) * HH + h) * WW + w;
#pragma unroll
    for (int c = 0; c < 16; ++c) g_avg[outbase + c * HW] = acc[c];
}

// ============================================================
// Kernel 3b: weights -> fp16 per tap. grid 49.
// ============================================================
__global__ __launch_bounds__(256) void k_prepw(const float* __restrict__ fw) {
    int t = blockIdx.x;
    for (int e = threadIdx.x; e < CC * CC; e += 256) {
        int co = e >> 6, ci = e & 63;
        float v = fw[(size_t)(co * CC + ci) * 49 + t];
        g_wt[(size_t)t * (CC * CC) + e] = __half_as_ushort(__float2half_rn(v));
    }
}

// ============================================================
// Kernel 4: 7x7 conv via mma.sync implicit GEMM, taps-outer / K=ci.
// NEW: M tile 256 px (8h x 32w) -> 143 blocks/batch, single wave at
// 2 blocks/SM; A build + barriers amortized over 2x MMAs. x4 B ldmatrix.
// Partial last h-tile (rows 96..99) guarded in epilogue; A build clamps.
// ============================================================
#define ASTRIDE 144
#define EXT_ROWS 14                        // 8 + 6 halo
#define EXT_PX (EXT_ROWS * 38)             // 532
#define AS_SZ (EXT_PX * ASTRIDE)           // 76608
#define BS_OFF(buf) (AS_SZ + (buf) * 9216)
#define SMEM_TC (AS_SZ + 2 * 9216)         // 95040

__global__ void __launch_bounds__(256, 2) k_conv_mma(float* __restrict__ out,
                                                     const float* __restrict__ bias, int b) {
    extern __shared__ unsigned char smem[];
    uint32_t sb = smem_u32(smem);
    int tid = threadIdx.x;
    int lane = tid & 31, wrp = tid >> 5;
    int mw = wrp & 3, nw = wrp >> 2;
    int h0 = blockIdx.y * 8, w0 = blockIdx.x * 32;

    float acc[4][4][4];
#pragma unroll
    for (int mt = 0; mt < 4; ++mt)
#pragma unroll
        for (int nt = 0; nt < 4; ++nt)
#pragma unroll
            for (int r = 0; r < 4; ++r) acc[mt][nt][r] = 0.0f;

    int tl = lane >> 3;
    int a_roff = (lane & 7) + (tl & 1) * 8;
    int a_coff = (tl >> 1) * 8;
    // B x4 lane mapping (validated R15)
    int b4_roff = (lane & 7) + ((lane >> 4) & 1) * 8;
    int b4_coff = ((lane >> 3) & 1) * 8;

    uint32_t aBase[4];
#pragma unroll
    for (int mt = 0; mt < 4; ++mt) {
        int px = mw * 64 + mt * 16 + a_roff;   // 0..255 block-pixel
        int pr = px >> 5, pc = px & 31;
        aBase[mt] = sb + (uint32_t)(pr * 38 + pc) * ASTRIDE + (uint32_t)a_coff * 2;
    }
    uint32_t bBase4 = (uint32_t)(nw * 32 + b4_roff) * ASTRIDE + (uint32_t)b4_coff * 2;

    int b_co0 = tid >> 3, b_f4 = tid & 7;

    const float* inb = g_avg + (size_t)b * CC * HW;

    // ---- build A_ext once: 532 ext px x 64 ci, fp16 (rows >= HH clamp to 0) ----
#pragma unroll 4
    for (int it = 0; it < 136; ++it) {
        int idx = tid + it * 256;              // 64 ci * 544 slots = 34816
        int ci = idx / 544, p = idx - ci * 544;
        if (p < EXT_PX) {
            int er = p / 38, ec = p - er * 38;
            int gh = h0 - 3 + er, gw = w0 - 3 + ec;
            float v = 0.0f;
            if (gh >= 0 && gh < HH && gw >= 0 && gw < WW) v = inb[(size_t)ci * HW + gh * WW + gw];
            *(unsigned short*)(smem + p * ASTRIDE + ci * 2) =
                __half_as_ushort(__float2half_rn(v));
        }
    }
    // ---- stage B tap 0 into buffer 0 ----
    {
        const float4* s0 = (const float4*)(g_wt);
        float4* d0 = (float4*)(smem + BS_OFF(0));
        d0[b_co0 * 9 + b_f4] = s0[tid];
        d0[(b_co0 + 32) * 9 + b_f4] = s0[tid + 256];
    }
    __syncthreads();

    int toff = 0;
    int kx = 0;
    for (int t = 0; t < 49; ++t) {
        int buf = t & 1;
        bool have_next = (t + 1 < 49);
        float4 v0, v1;
        if (have_next) {
            const float4* s0 = (const float4*)(g_wt + (size_t)(t + 1) * (CC * CC));
            v0 = s0[tid]; v1 = s0[tid + 256];
        }

        uint32_t bptr = sb + BS_OFF(buf) + bBase4;
#pragma unroll
        for (int j = 0; j < 4; ++j) {
            uint32_t Ah[4][4];
#pragma unroll
            for (int mt = 0; mt < 4; ++mt)
                LDMATRIX_X4(Ah[mt], aBase[mt] + (uint32_t)toff + (uint32_t)j * 32);
#pragma unroll
            for (int p = 0; p < 2; ++p) {
                uint32_t Bf[4];
                LDMATRIX_X4(Bf, bptr + (uint32_t)(p * 16) * ASTRIDE + (uint32_t)j * 32);
#pragma unroll
                for (int mt = 0; mt < 4; ++mt) {
                    MMA_F16(acc[mt][p * 2], Ah[mt], Bf);
                    MMA_F16(acc[mt][p * 2 + 1], Ah[mt], Bf + 2);
                }
            }
        }

        if (have_next) {
            int nb = buf ^ 1;
            float4* d0 = (float4*)(smem + BS_OFF(nb));
            d0[b_co0 * 9 + b_f4] = v0;
            d0[(b_co0 + 32) * 9 + b_f4] = v1;
        }
        __syncthreads();

        ++kx;
        if (kx == 7) { kx = 0; toff += 32 * ASTRIDE; }
        else toff += ASTRIDE;
    }

    // ---- epilogue (guard oh < HH for the partial last h-tile) ----
    int g = lane >> 2, tig = lane & 3;
    float* o = out + (size_t)b * CC * HW;
#pragma unroll
    for (int mt = 0; mt < 4; ++mt) {
        int r0 = mw * 64 + mt * 16 + g;
        int oh0 = h0 + (r0 >> 5), ow0 = w0 + (r0 & 31);
        int r1 = r0 + 8;
        int oh1 = h0 + (r1 >> 5), ow1 = w0 + (r1 & 31);
        bool ok0 = oh0 < HH, ok1 = oh1 < HH;
#pragma unroll
        for (int nt = 0; nt < 4; ++nt) {
            int co = nw * 32 + nt * 8 + tig * 2;
            float bv0 = __ldg(&bias[co]), bv1 = __ldg(&bias[co + 1]);
            if (ok0) {
                o[(size_t)co * HW + oh0 * WW + ow0] = acc[mt][nt][0] + bv0;
                o[(size_t)(co + 1) * HW + oh0 * WW + ow0] = acc[mt][nt][1] + bv1;
            }
            if (ok1) {
                o[(size_t)co * HW + oh1 * WW + ow1] = acc[mt][nt][2] + bv0;
                o[(size_t)(co + 1) * HW + oh1 * WW + ow1] = acc[mt][nt][3] + bv1;
            }
        }
    }
}

// ============================================================
// Launch: two per-batch chains forked onto a second stream via events.
// ============================================================
extern "C" void kernel_launch(void* const* d_in, const int* in_sizes, int n_in,
                              void* d_out, int out_size) {
    const float* x   = (const float*)d_in[0];  // (10,64,100,352)
    const float* psm = (const float*)d_in[1];  // (10,2,100,352)
    // d_in[2] record_len: unused
    const float* pt  = (const float*)d_in[3];  // (2,5,5,4,4)
    const float* fw  = (const float*)d_in[4];  // (64,64,7,7)
    const float* fb  = (const float*)d_in[5];  // (64,)
    float* out = (float*)d_out;                // (2,64,100,352)

    static bool inited = false;
    static cudaStream_t sB = 0;
    static cudaEvent_t evF0 = 0, evP = 0, evJ1 = 0;
    if (!inited) {
        cudaFuncSetAttribute(k_conv_mma, cudaFuncAttributeMaxDynamicSharedMemorySize, SMEM_TC);
        cudaFuncSetAttribute(k_select, cudaFuncAttributeMaxDynamicSharedMemorySize, SEL_SMEM);
        if (cudaStreamCreateWithFlags(&sB, cudaStreamNonBlocking) != cudaSuccess) sB = 0;
        if (sB) {
            if (cudaEventCreateWithFlags(&evF0, cudaEventDisableTiming) != cudaSuccess ||
                cudaEventCreateWithFlags(&evP, cudaEventDisableTiming) != cudaSuccess ||
                cudaEventCreateWithFlags(&evJ1, cudaEventDisableTiming) != cudaSuccess) {
                sB = 0;
            }
        }
        inited = true;
    }

    const int nconf = (LL * HW + 255) / 256;
    const dim3 convGrid(WW / 32, (HH + 7) / 8, 1);   // 11 x 13

    if (sB) {
        cudaEventRecord(evF0, 0);
        cudaStreamWaitEvent(sB, evF0, 0);

        // stream sB: batch 1 chain (+ weight prep, consumed by both convs)
        k_prepw<<<49, 256, 0, sB>>>(fw);
        cudaEventRecord(evP, sB);
        k_conf<<<nconf, 256, 0, sB>>>(psm, LL);
        k_confwarp<<<dim3(HH, LL), WW, 0, sB>>>(pt, LL);
        k_select<<<LL, 1024, SEL_SMEM, sB>>>(LL);
        k_warpacc<<<dim3(HH, 4, 1), WW, 0, sB>>>(x, pt, 1);
        k_conv_mma<<<convGrid, 256, SMEM_TC, sB>>>(out, fb, 1);
        cudaEventRecord(evJ1, sB);

        // stream 0: batch 0 chain
        k_conf<<<nconf, 256>>>(psm, 0);
        k_confwarp<<<dim3(HH, LL), WW>>>(pt, 0);
        k_select<<<LL, 1024, SEL_SMEM>>>(0);
        k_warpacc<<<dim3(HH, 4, 1), WW>>>(x, pt, 0);
        cudaStreamWaitEvent(0, evP, 0);
        k_conv_mma<<<convGrid, 256, SMEM_TC>>>(out, fb, 0);

        cudaStreamWaitEvent(0, evJ1, 0);
    } else {
        // fallback: single-stream sequence
        k_prepw<<<49, 256>>>(fw);
        k_conf<<<nconf, 256>>>(psm, 0);
        k_conf<<<nconf, 256>>>(psm, LL);
        k_confwarp<<<dim3(HH, LL), WW>>>(pt, 0);
        k_confwarp<<<dim3(HH, LL), WW>>>(pt, LL);
        k_select<<<LL, 1024, SEL_SMEM>>>(0);
        k_select<<<LL, 1024, SEL_SMEM>>>(LL);
        k_warpacc<<<dim3(HH, 4, 1), WW>>>(x, pt, 0);
        k_warpacc<<<dim3(HH, 4, 1), WW>>>(x, pt, 1);
        k_conv_mma<<<convGrid, 256, SMEM_TC>>>(out, fb, 0);
        k_conv_mma<<<convGrid, 256, SMEM_TC>>>(out, fb, 1);
    }
}